// round 12
// baseline (speedup 1.0000x reference)
#include <cuda_runtime.h>

// Problem constants
#define Tn 336
#define Fn 12
#define Hn 50
#define Bn 4096
#define BC 32          // batch rows per CTA
#define NTHREADS 512
#define RPG 4          // rows per group (8 groups x 2 warps)
#define HPAD 52        // h row stride (16B-multiple)

// shared memory float offsets.
// Weight arrays store j-PAIRS per gate, A half = gates(i,f), B half = gates(g,o):
//   A[(p*50+u)*4 + {i_j0,i_j1,f_j0,f_j1}]  (16B per (p,u), conflict-free in u)
// B half at fixed +1200 (x-part) or +5000 (h-parts) floats.
#define W0XA_OFF 0        // layer0 x-part A: 1200  (B at +1200)
#define W0HA_OFF 2400     // layer0 h-part A: 5000  (B at +5000)
#define W1IA_OFF 12400    // layer1 input(h0)
#define W1RA_OFF 22400    // layer1 recurrent(h1)
#define W2IA_OFF 32400    // layer2 input(h1)
#define W2RA_OFF 42400    // layer2 recurrent(h2)
#define HS_OFF   52400    // h state  3 * 32 * 52 = 4992
#define XS_OFF   57392    // x tile   32 * 12 = 384
#define SMEM_FLOATS 57776
#define SMEM_BYTES (SMEM_FLOATS * 4)

typedef unsigned long long u64;

// packed dual-fp32 FMA (sm_103a FFMA2): z += w * h (elementwise, 2 fp32 lanes)
__device__ __forceinline__ void ffma2(u64& z, const u64 w, const u64 h) {
    asm("fma.rn.f32x2 %0, %1, %2, %0;" : "+l"(z) : "l"(w), "l"(h));
}
__device__ __forceinline__ void unpack2(const u64 v, float& lo, float& hi) {
    asm("mov.b64 {%0, %1}, %2;" : "=f"(lo), "=f"(hi) : "l"(v));
}

__device__ __forceinline__ float sigmoidf_(float v) {
    return 1.0f / (1.0f + __expf(-v));
}
// precise-enough tanh: 1 - 2/(1+e^{2x}); ~1e-7 rel err
__device__ __forceinline__ float tanhf_(float v) {
    const float e = __expf(2.0f * v);
    return 1.0f - 2.0f / (e + 1.0f);
}

// named barrier for a 2-warp group (ids 1..8; 0 reserved for __syncthreads)
__device__ __forceinline__ void barg(int id) {
    asm volatile("bar.sync %0, 64;" :: "r"(id) : "memory");
}

// 25 j-pairs over a 50-long vector (stride HPAD). BO = float offset A->B half.
// Pointer-bump addressing only: one weight pointer (+imm offsets), one h pointer.
template<int BO>
__device__ __forceinline__ void accH(u64 zi[RPG], u64 zf[RPG], u64 zg[RPG], u64 zo[RPG],
                                     const float* __restrict__ WA,
                                     const float* __restrict__ hb, int u)
{
    const float* wa = WA + u*4;
    const float* hq = hb;
#pragma unroll 1
    for (int p = 0; p < 24; p += 2) {
        const ulonglong2 wa0 = *(const ulonglong2*)(wa);
        const ulonglong2 wb0 = *(const ulonglong2*)(wa + BO);
        const ulonglong2 wa1 = *(const ulonglong2*)(wa + 200);
        const ulonglong2 wb1 = *(const ulonglong2*)(wa + BO + 200);
#pragma unroll
        for (int r = 0; r < RPG; r++) {
            const ulonglong2 hv = *(const ulonglong2*)(hq + r*HPAD);  // pairs (p),(p+1)
            ffma2(zi[r], wa0.x, hv.x); ffma2(zf[r], wa0.y, hv.x);
            ffma2(zg[r], wb0.x, hv.x); ffma2(zo[r], wb0.y, hv.x);
            ffma2(zi[r], wa1.x, hv.y); ffma2(zf[r], wa1.y, hv.y);
            ffma2(zg[r], wb1.x, hv.y); ffma2(zo[r], wb1.y, hv.y);
        }
        wa += 400; hq += 4;
    }
    // remainder pair p=24 (j=48,49); hq at +48 (16B-aligned, 8B load)
    const ulonglong2 waR = *(const ulonglong2*)(wa);
    const ulonglong2 wbR = *(const ulonglong2*)(wa + BO);
#pragma unroll
    for (int r = 0; r < RPG; r++) {
        const u64 hp_ = *(const u64*)(hq + r*HPAD);
        ffma2(zi[r], waR.x, hp_); ffma2(zf[r], waR.y, hp_);
        ffma2(zg[r], wbR.x, hp_); ffma2(zo[r], wbR.y, hp_);
    }
}

// 6 j-pairs over the 12-long x vector (stride Fn). BO = float offset A->B half.
template<int BO>
__device__ __forceinline__ void accX(u64 zi[RPG], u64 zf[RPG], u64 zg[RPG], u64 zo[RPG],
                                     const float* __restrict__ WA,
                                     const float* __restrict__ xr, int u)
{
    const float* wa = WA + u*4;
    const float* xq = xr;
#pragma unroll 1
    for (int p = 0; p < 6; p += 2) {
        const ulonglong2 wa0 = *(const ulonglong2*)(wa);
        const ulonglong2 wb0 = *(const ulonglong2*)(wa + BO);
        const ulonglong2 wa1 = *(const ulonglong2*)(wa + 200);
        const ulonglong2 wb1 = *(const ulonglong2*)(wa + BO + 200);
#pragma unroll
        for (int r = 0; r < RPG; r++) {
            const ulonglong2 hv = *(const ulonglong2*)(xq + r*Fn);
            ffma2(zi[r], wa0.x, hv.x); ffma2(zf[r], wa0.y, hv.x);
            ffma2(zg[r], wb0.x, hv.x); ffma2(zo[r], wb0.y, hv.x);
            ffma2(zi[r], wa1.x, hv.y); ffma2(zf[r], wa1.y, hv.y);
            ffma2(zg[r], wb1.x, hv.y); ffma2(zo[r], wb1.y, hv.y);
        }
        wa += 400; xq += 4;
    }
}

__global__ void __launch_bounds__(NTHREADS, 1)
lstm_fused(const float* __restrict__ x,
           const float* __restrict__ Wih0, const float* __restrict__ Whh0,
           const float* __restrict__ bih0, const float* __restrict__ bhh0,
           const float* __restrict__ Wih1, const float* __restrict__ Whh1,
           const float* __restrict__ bih1, const float* __restrict__ bhh1,
           const float* __restrict__ Wih2, const float* __restrict__ Whh2,
           const float* __restrict__ bih2, const float* __restrict__ bhh2,
           const float* __restrict__ Wlin, const float* __restrict__ blin,
           float* __restrict__ out)
{
    extern __shared__ float sm[];
    float* HS = sm + HS_OFF;   // [3][BC][HPAD]
    float* XS = sm + XS_OFF;   // [BC][12]

    const int tid   = threadIdx.x;
    const int lane  = tid & 31;
    const int wid   = tid >> 5;
    const int grp   = wid >> 1;               // 0..7
    const int bid   = grp + 1;                // named barrier id
    const int r0    = grp * RPG;              // row base (4 rows)
    const int u     = (wid & 1) * 32 + lane;  // unit id
    const bool act  = (u < Hn);
    const int gtid  = tid & 63;               // thread id within group

    // ---- stage weights: j-pair A/B halves ----
    // layer0 x-part: 6 pairs from Wih0 [4H x 12]
    for (int idx = tid; idx < 1200; idx += NTHREADS) {
        const int uu = (idx >> 2) % 50;
        const int p  = idx / 200;
        const int jj = idx & 1;
        const int gh = (idx >> 1) & 1;
        const int j  = 2*p + jj;
        sm[W0XA_OFF + idx]        = Wih0[((0 + gh)*50 + uu)*12 + j];
        sm[W0XA_OFF + 1200 + idx] = Wih0[((2 + gh)*50 + uu)*12 + j];
    }
    // 25-pair blocks from [4H x 50] sources
    {
        const float* srcs[5] = { Whh0, Wih1, Whh1, Wih2, Whh2 };
        const int offA[5] = { W0HA_OFF, W1IA_OFF, W1RA_OFF, W2IA_OFF, W2RA_OFF };
#pragma unroll 1
        for (int s = 0; s < 5; s++) {
            const float* Wsrc = srcs[s];
            float* A = sm + offA[s];
            for (int idx = tid; idx < 5000; idx += NTHREADS) {
                const int uu = (idx >> 2) % 50;
                const int p  = idx / 200;
                const int jj = idx & 1;
                const int gh = (idx >> 1) & 1;
                const int j  = 2*p + jj;
                A[idx]        = Wsrc[((0 + gh)*50 + uu)*50 + j];
                A[5000 + idx] = Wsrc[((2 + gh)*50 + uu)*50 + j];
            }
        }
    }
    for (int idx = tid; idx < 3*BC*HPAD; idx += NTHREADS) HS[idx] = 0.0f;

    // biases as plain floats (added in the horizontal reduction)
    float bi0=0.f,bf0=0.f,bg0=0.f,bo0=0.f;
    float bi1=0.f,bf1=0.f,bg1=0.f,bo1=0.f;
    float bi2=0.f,bf2=0.f,bg2=0.f,bo2=0.f;
    if (act) {
        bi0 = bih0[u]       + bhh0[u];
        bf0 = bih0[50 + u]  + bhh0[50 + u];
        bg0 = bih0[100 + u] + bhh0[100 + u];
        bo0 = bih0[150 + u] + bhh0[150 + u];
        bi1 = bih1[u]       + bhh1[u];
        bf1 = bih1[50 + u]  + bhh1[50 + u];
        bg1 = bih1[100 + u] + bhh1[100 + u];
        bo1 = bih1[150 + u] + bhh1[150 + u];
        bi2 = bih2[u]       + bhh2[u];
        bf2 = bih2[50 + u]  + bhh2[50 + u];
        bg2 = bih2[100 + u] + bhh2[100 + u];
        bo2 = bih2[150 + u] + bhh2[150 + u];
    }

    float c0[RPG], c1[RPG], c2[RPG];
#pragma unroll
    for (int r = 0; r < RPG; r++) { c0[r] = 0.f; c1[r] = 0.f; c2[r] = 0.f; }

    const long long bbase = (long long)blockIdx.x * BC;
    const float* xb = x + bbase * (Tn * Fn);

    // group loads its own 4 rows x 12 = 48 x-values (gtid < 48)
    const int xrow = r0 + gtid / Fn;
    const int xcol = gtid % Fn;

    __syncthreads();

    float* HS0 = HS + 0*(BC*HPAD) + r0*HPAD;
    float* HS1 = HS + 1*(BC*HPAD) + r0*HPAD;
    float* HS2 = HS + 2*(BC*HPAD) + r0*HPAD;
    float* XSg = XS + r0*Fn;

    for (int t = 0; t < Tn; t++) {
        // ---- group-local x tile load: 4 rows x 12 ----
        if (gtid < RPG*Fn)
            XSg[gtid] = xb[xrow*(Tn*Fn) + t*Fn + xcol];
        barg(bid);

        float hn[RPG];
        u64 zi[RPG], zf[RPG], zg[RPG], zo[RPG];

        // ================= layer 0 =================
        if (act) {
#pragma unroll
            for (int r = 0; r < RPG; r++) { zi[r]=0; zf[r]=0; zg[r]=0; zo[r]=0; }
            accX<1200>(zi, zf, zg, zo, sm + W0XA_OFF, XSg, u);
            accH<5000>(zi, zf, zg, zo, sm + W0HA_OFF, HS0, u);
#pragma unroll
            for (int r = 0; r < RPG; r++) {
                float a, b;
                unpack2(zi[r], a, b); const float si = a + b + bi0;
                unpack2(zf[r], a, b); const float sf = a + b + bf0;
                unpack2(zg[r], a, b); const float sg = a + b + bg0;
                unpack2(zo[r], a, b); const float so = a + b + bo0;
                const float ig = sigmoidf_(si);
                const float fg = sigmoidf_(sf);
                const float gg = tanhf_(sg);
                const float og = sigmoidf_(so);
                c0[r] = fg * c0[r] + ig * gg;
                hn[r] = og * tanhf_(c0[r]);
            }
        }
        barg(bid);
        if (act) {
#pragma unroll
            for (int r = 0; r < RPG; r++) HS0[r*HPAD + u] = hn[r];
        }
        barg(bid);

        // ================= layer 1 =================
        if (act) {
#pragma unroll
            for (int r = 0; r < RPG; r++) { zi[r]=0; zf[r]=0; zg[r]=0; zo[r]=0; }
            accH<5000>(zi, zf, zg, zo, sm + W1IA_OFF, HS0, u);
            accH<5000>(zi, zf, zg, zo, sm + W1RA_OFF, HS1, u);
#pragma unroll
            for (int r = 0; r < RPG; r++) {
                float a, b;
                unpack2(zi[r], a, b); const float si = a + b + bi1;
                unpack2(zf[r], a, b); const float sf = a + b + bf1;
                unpack2(zg[r], a, b); const float sg = a + b + bg1;
                unpack2(zo[r], a, b); const float so = a + b + bo1;
                const float ig = sigmoidf_(si);
                const float fg = sigmoidf_(sf);
                const float gg = tanhf_(sg);
                const float og = sigmoidf_(so);
                c1[r] = fg * c1[r] + ig * gg;
                hn[r] = og * tanhf_(c1[r]);
            }
        }
        barg(bid);
        if (act) {
#pragma unroll
            for (int r = 0; r < RPG; r++) HS1[r*HPAD + u] = hn[r];
        }
        barg(bid);

        // ================= layer 2 =================
        if (act) {
#pragma unroll
            for (int r = 0; r < RPG; r++) { zi[r]=0; zf[r]=0; zg[r]=0; zo[r]=0; }
            accH<5000>(zi, zf, zg, zo, sm + W2IA_OFF, HS1, u);
            accH<5000>(zi, zf, zg, zo, sm + W2RA_OFF, HS2, u);
#pragma unroll
            for (int r = 0; r < RPG; r++) {
                float a, b;
                unpack2(zi[r], a, b); const float si = a + b + bi2;
                unpack2(zf[r], a, b); const float sf = a + b + bf2;
                unpack2(zg[r], a, b); const float sg = a + b + bg2;
                unpack2(zo[r], a, b); const float so = a + b + bo2;
                const float ig = sigmoidf_(si);
                const float fg = sigmoidf_(sf);
                const float gg = tanhf_(sg);
                const float og = sigmoidf_(so);
                c2[r] = fg * c2[r] + ig * gg;
                hn[r] = og * tanhf_(c2[r]);
            }
        }
        barg(bid);
        if (act) {
#pragma unroll
            for (int r = 0; r < RPG; r++) HS2[r*HPAD + u] = hn[r];
        }
        barg(bid);
    }

    __syncthreads();

    // ---- final linear: out[b] = h2[b] . Wlin + blin ----
    if (tid < BC) {
        float s = blin[0];
#pragma unroll 10
        for (int uu = 0; uu < Hn; uu++)
            s += HS[2*(BC*HPAD) + tid*HPAD + uu] * Wlin[uu];
        out[bbase + tid] = s;
    }
}

extern "C" void kernel_launch(void* const* d_in, const int* in_sizes, int n_in,
                              void* d_out, int out_size)
{
    (void)in_sizes; (void)n_in; (void)out_size;
    const float* x    = (const float*)d_in[0];
    const float* Wih0 = (const float*)d_in[1];
    const float* Whh0 = (const float*)d_in[2];
    const float* bih0 = (const float*)d_in[3];
    const float* bhh0 = (const float*)d_in[4];
    const float* Wih1 = (const float*)d_in[5];
    const float* Whh1 = (const float*)d_in[6];
    const float* bih1 = (const float*)d_in[7];
    const float* bhh1 = (const float*)d_in[8];
    const float* Wih2 = (const float*)d_in[9];
    const float* Whh2 = (const float*)d_in[10];
    const float* bih2 = (const float*)d_in[11];
    const float* bhh2 = (const float*)d_in[12];
    const float* Wlin = (const float*)d_in[13];
    const float* blin = (const float*)d_in[14];
    float* out = (float*)d_out;

    cudaFuncSetAttribute(lstm_fused, cudaFuncAttributeMaxDynamicSharedMemorySize, SMEM_BYTES);
    lstm_fused<<<Bn / BC, NTHREADS, SMEM_BYTES>>>(
        x, Wih0, Whh0, bih0, bhh0,
        Wih1, Whh1, bih1, bhh1,
        Wih2, Whh2, bih2, bhh2,
        Wlin, blin, out);
}

// round 13
// speedup vs baseline: 1.3214x; 1.3214x over previous
#include <cuda_runtime.h>

// Problem constants
#define Tn 336
#define Fn 12
#define Hn 50
#define Bn 4096
#define BC 32          // batch rows per CTA
#define NTHREADS 512
#define HPAD 52        // h row stride (float4-aligned)
#define RPG 4          // rows per group (8 groups x 2 warps)

// shared memory float offsets
#define W0_OFF 0                 // layer0 combined [62][50][4]  = 12400 floats
#define W1_OFF 12400             // layer1 combined [100][50][4] = 20000
#define W2_OFF 32400             // layer2 combined [100][50][4] = 20000
#define HS_OFF 52400             // h state  3 * 32 * 52 = 4992
#define XS_OFF 57392             // x tile   32 * 12 = 384
#define SMEM_FLOATS 57776
#define SMEM_BYTES (SMEM_FLOATS * 4)

typedef unsigned long long u64;

// packed dual-fp32 FMA (sm_103a FFMA2): z += w * h (elementwise on 2 lanes)
__device__ __forceinline__ void ffma2(u64& z, const u64 w, const u64 h) {
    asm("fma.rn.f32x2 %0, %1, %2, %0;" : "+l"(z) : "l"(w), "l"(h));
}
// broadcast a scalar into both halves of a b64
__device__ __forceinline__ u64 dup2(const float s) {
    u64 r; asm("mov.b64 %0, {%1, %1};" : "=l"(r) : "f"(s)); return r;
}
__device__ __forceinline__ u64 pack2(const float lo, const float hi) {
    u64 r; asm("mov.b64 %0, {%1, %2};" : "=l"(r) : "f"(lo), "f"(hi)); return r;
}
__device__ __forceinline__ void unpack2(const u64 v, float& lo, float& hi) {
    asm("mov.b64 {%0, %1}, %2;" : "=f"(lo), "=f"(hi) : "l"(v));
}

__device__ __forceinline__ float sigmoidf_(float v) {
    return 1.0f / (1.0f + __expf(-v));
}
// precise-enough tanh: 1 - 2/(1+e^{2x}); ~1e-7 rel err
__device__ __forceinline__ float tanhf_(float v) {
    const float e = __expf(2.0f * v);
    return 1.0f - 2.0f / (e + 1.0f);
}

// named barrier for a 2-warp group (ids 1..8; 0 reserved for __syncthreads)
__device__ __forceinline__ void barg(int id) {
    asm volatile("bar.sync %0, 64;" :: "r"(id) : "memory");
}

struct Z2 { u64 a, b; };   // a = gates (i,f), b = gates (g,o)

// z[r] += sum_{j<50} W[j][u][:] * h[r][j]  (R5's exact pattern)
__device__ __forceinline__ void acc50(Z2 z[RPG], const float* __restrict__ Wb,
                                      const float* __restrict__ hb, int u)
{
#pragma unroll 1
    for (int jb = 0; jb < 48; jb += 4) {
        const ulonglong2 w0 = *(const ulonglong2*)(Wb + ((jb+0)*50 + u)*4);
        const ulonglong2 w1 = *(const ulonglong2*)(Wb + ((jb+1)*50 + u)*4);
        const ulonglong2 w2 = *(const ulonglong2*)(Wb + ((jb+2)*50 + u)*4);
        const ulonglong2 w3 = *(const ulonglong2*)(Wb + ((jb+3)*50 + u)*4);
#pragma unroll
        for (int r = 0; r < RPG; r++) {
            const float4 hv = *(const float4*)(hb + r*HPAD + jb);
            const u64 h0 = dup2(hv.x);
            const u64 h1 = dup2(hv.y);
            const u64 h2 = dup2(hv.z);
            const u64 h3 = dup2(hv.w);
            ffma2(z[r].a, w0.x, h0); ffma2(z[r].b, w0.y, h0);
            ffma2(z[r].a, w1.x, h1); ffma2(z[r].b, w1.y, h1);
            ffma2(z[r].a, w2.x, h2); ffma2(z[r].b, w2.y, h2);
            ffma2(z[r].a, w3.x, h3); ffma2(z[r].b, w3.y, h3);
        }
    }
    const ulonglong2 w48 = *(const ulonglong2*)(Wb + (48*50 + u)*4);
    const ulonglong2 w49 = *(const ulonglong2*)(Wb + (49*50 + u)*4);
#pragma unroll
    for (int r = 0; r < RPG; r++) {
        const u64 h48 = dup2(hb[r*HPAD + 48]);
        const u64 h49 = dup2(hb[r*HPAD + 49]);
        ffma2(z[r].a, w48.x, h48); ffma2(z[r].b, w48.y, h48);
        ffma2(z[r].a, w49.x, h49); ffma2(z[r].b, w49.y, h49);
    }
}

// merged double accumulation: z += Wa.h_a + Wb.h_b in one loop (2x ILP per iter)
__device__ __forceinline__ void acc50x2(Z2 z[RPG],
                                        const float* __restrict__ Wa,
                                        const float* __restrict__ ha,
                                        const float* __restrict__ Wb,
                                        const float* __restrict__ hb, int u)
{
#pragma unroll 1
    for (int jb = 0; jb < 48; jb += 4) {
        const ulonglong2 a0 = *(const ulonglong2*)(Wa + ((jb+0)*50 + u)*4);
        const ulonglong2 a1 = *(const ulonglong2*)(Wa + ((jb+1)*50 + u)*4);
        const ulonglong2 a2 = *(const ulonglong2*)(Wa + ((jb+2)*50 + u)*4);
        const ulonglong2 a3 = *(const ulonglong2*)(Wa + ((jb+3)*50 + u)*4);
        const ulonglong2 b0 = *(const ulonglong2*)(Wb + ((jb+0)*50 + u)*4);
        const ulonglong2 b1 = *(const ulonglong2*)(Wb + ((jb+1)*50 + u)*4);
        const ulonglong2 b2 = *(const ulonglong2*)(Wb + ((jb+2)*50 + u)*4);
        const ulonglong2 b3 = *(const ulonglong2*)(Wb + ((jb+3)*50 + u)*4);
#pragma unroll
        for (int r = 0; r < RPG; r++) {
            const float4 hva = *(const float4*)(ha + r*HPAD + jb);
            const float4 hvb = *(const float4*)(hb + r*HPAD + jb);
            const u64 ha0 = dup2(hva.x);
            const u64 ha1 = dup2(hva.y);
            const u64 ha2 = dup2(hva.z);
            const u64 ha3 = dup2(hva.w);
            ffma2(z[r].a, a0.x, ha0); ffma2(z[r].b, a0.y, ha0);
            ffma2(z[r].a, a1.x, ha1); ffma2(z[r].b, a1.y, ha1);
            ffma2(z[r].a, a2.x, ha2); ffma2(z[r].b, a2.y, ha2);
            ffma2(z[r].a, a3.x, ha3); ffma2(z[r].b, a3.y, ha3);
            const u64 hb0 = dup2(hvb.x);
            const u64 hb1 = dup2(hvb.y);
            const u64 hb2 = dup2(hvb.z);
            const u64 hb3 = dup2(hvb.w);
            ffma2(z[r].a, b0.x, hb0); ffma2(z[r].b, b0.y, hb0);
            ffma2(z[r].a, b1.x, hb1); ffma2(z[r].b, b1.y, hb1);
            ffma2(z[r].a, b2.x, hb2); ffma2(z[r].b, b2.y, hb2);
            ffma2(z[r].a, b3.x, hb3); ffma2(z[r].b, b3.y, hb3);
        }
    }
    const ulonglong2 a48 = *(const ulonglong2*)(Wa + (48*50 + u)*4);
    const ulonglong2 a49 = *(const ulonglong2*)(Wa + (49*50 + u)*4);
    const ulonglong2 b48 = *(const ulonglong2*)(Wb + (48*50 + u)*4);
    const ulonglong2 b49 = *(const ulonglong2*)(Wb + (49*50 + u)*4);
#pragma unroll
    for (int r = 0; r < RPG; r++) {
        const u64 ha48 = dup2(ha[r*HPAD + 48]);
        const u64 ha49 = dup2(ha[r*HPAD + 49]);
        const u64 hb48 = dup2(hb[r*HPAD + 48]);
        const u64 hb49 = dup2(hb[r*HPAD + 49]);
        ffma2(z[r].a, a48.x, ha48); ffma2(z[r].b, a48.y, ha48);
        ffma2(z[r].a, a49.x, ha49); ffma2(z[r].b, a49.y, ha49);
        ffma2(z[r].a, b48.x, hb48); ffma2(z[r].b, b48.y, hb48);
        ffma2(z[r].a, b49.x, hb49); ffma2(z[r].b, b49.y, hb49);
    }
}

__global__ void __launch_bounds__(NTHREADS, 1)
lstm_fused(const float* __restrict__ x,
           const float* __restrict__ Wih0, const float* __restrict__ Whh0,
           const float* __restrict__ bih0, const float* __restrict__ bhh0,
           const float* __restrict__ Wih1, const float* __restrict__ Whh1,
           const float* __restrict__ bih1, const float* __restrict__ bhh1,
           const float* __restrict__ Wih2, const float* __restrict__ Whh2,
           const float* __restrict__ bih2, const float* __restrict__ bhh2,
           const float* __restrict__ Wlin, const float* __restrict__ blin,
           float* __restrict__ out)
{
    extern __shared__ float sm[];
    float* W0 = sm + W0_OFF;
    float* W1 = sm + W1_OFF;
    float* W2 = sm + W2_OFF;
    float* HS = sm + HS_OFF;   // [3][BC][HPAD]
    float* XS = sm + XS_OFF;   // [BC][12]

    const int tid   = threadIdx.x;
    const int lane  = tid & 31;
    const int wid   = tid >> 5;
    const int grp   = wid >> 1;               // 0..7
    const int bid   = grp + 1;                // named barrier id
    const int r0    = grp * RPG;              // row base (4 rows)
    const int u     = (wid & 1) * 32 + lane;  // unit id
    const bool act  = (u < Hn);
    const int gtid  = tid & 63;               // thread id within group

    // ---- stage weights into shared with [k][u][gate] layout ----
    for (int idx = tid; idx < 12400; idx += NTHREADS) {
        const int g  = idx & 3;
        const int uu = (idx >> 2) % 50;
        const int k  = idx / 200;
        W0[idx] = (k < 12) ? Wih0[(g*50 + uu)*12 + k]
                           : Whh0[(g*50 + uu)*50 + (k - 12)];
    }
    for (int idx = tid; idx < 20000; idx += NTHREADS) {
        const int g  = idx & 3;
        const int uu = (idx >> 2) % 50;
        const int k  = idx / 200;
        W1[idx] = (k < 50) ? Wih1[(g*50 + uu)*50 + k]
                           : Whh1[(g*50 + uu)*50 + (k - 50)];
    }
    for (int idx = tid; idx < 20000; idx += NTHREADS) {
        const int g  = idx & 3;
        const int uu = (idx >> 2) % 50;
        const int k  = idx / 200;
        W2[idx] = (k < 50) ? Wih2[(g*50 + uu)*50 + k]
                           : Whh2[(g*50 + uu)*50 + (k - 50)];
    }
    for (int idx = tid; idx < 3*BC*HPAD; idx += NTHREADS) HS[idx] = 0.0f;

    u64 b0a = 0, b0b = 0, b1a = 0, b1b = 0, b2a = 0, b2b = 0;
    if (act) {
        b0a = pack2(bih0[u]       + bhh0[u],       bih0[50 + u]  + bhh0[50 + u]);
        b0b = pack2(bih0[100 + u] + bhh0[100 + u], bih0[150 + u] + bhh0[150 + u]);
        b1a = pack2(bih1[u]       + bhh1[u],       bih1[50 + u]  + bhh1[50 + u]);
        b1b = pack2(bih1[100 + u] + bhh1[100 + u], bih1[150 + u] + bhh1[150 + u]);
        b2a = pack2(bih2[u]       + bhh2[u],       bih2[50 + u]  + bhh2[50 + u]);
        b2b = pack2(bih2[100 + u] + bhh2[100 + u], bih2[150 + u] + bhh2[150 + u]);
    }

    float c0[RPG], c1[RPG], c2[RPG];
#pragma unroll
    for (int r = 0; r < RPG; r++) { c0[r] = 0.f; c1[r] = 0.f; c2[r] = 0.f; }

    const long long bbase = (long long)blockIdx.x * BC;
    const float* xb = x + bbase * (Tn * Fn);

    const int xrow = r0 + gtid / Fn;          // valid if gtid < 48
    const int xcol = gtid % Fn;

    float* HS0 = HS + 0*(BC*HPAD) + r0*HPAD;
    float* HS1 = HS + 1*(BC*HPAD) + r0*HPAD;
    float* HS2 = HS + 2*(BC*HPAD) + r0*HPAD;
    float* XSg = XS + r0*Fn;

    // prime x tile for t=0 (covered by the __syncthreads below)
    if (gtid < RPG*Fn)
        XSg[gtid] = xb[xrow*(Tn*Fn) + 0*Fn + xcol];

    __syncthreads();

    for (int t = 0; t < Tn; t++) {
        float hn[RPG];
        Z2 z[RPG];

        // ================= layer 0 ================= (XS(t) ready from prev iter)
        if (act) {
#pragma unroll
            for (int r = 0; r < RPG; r++) { z[r].a = b0a; z[r].b = b0b; }
#pragma unroll
            for (int k = 0; k < 12; k++) {
                const ulonglong2 w = *(const ulonglong2*)(W0 + (k*50 + u)*4);
#pragma unroll
                for (int r = 0; r < RPG; r++) {
                    const u64 xv = dup2(XSg[r*Fn + k]);
                    ffma2(z[r].a, w.x, xv);
                    ffma2(z[r].b, w.y, xv);
                }
            }
            acc50(z, W0 + 12*200, HS0, u);
#pragma unroll
            for (int r = 0; r < RPG; r++) {
                float zi, zf, zg, zo;
                unpack2(z[r].a, zi, zf);
                unpack2(z[r].b, zg, zo);
                const float ig = sigmoidf_(zi);
                const float fg = sigmoidf_(zf);
                const float gg = tanhf_(zg);
                const float og = sigmoidf_(zo);
                c0[r] = fg * c0[r] + ig * gg;
                hn[r] = og * tanhf_(c0[r]);
            }
        }
        barg(bid);
        if (act) {
#pragma unroll
            for (int r = 0; r < RPG; r++) HS0[r*HPAD + u] = hn[r];
        }
        barg(bid);

        // ================= layer 1 ================= (merged dual acc)
        if (act) {
#pragma unroll
            for (int r = 0; r < RPG; r++) { z[r].a = b1a; z[r].b = b1b; }
            acc50x2(z, W1, HS0, W1 + 50*200, HS1, u);
#pragma unroll
            for (int r = 0; r < RPG; r++) {
                float zi, zf, zg, zo;
                unpack2(z[r].a, zi, zf);
                unpack2(z[r].b, zg, zo);
                const float ig = sigmoidf_(zi);
                const float fg = sigmoidf_(zf);
                const float gg = tanhf_(zg);
                const float og = sigmoidf_(zo);
                c1[r] = fg * c1[r] + ig * gg;
                hn[r] = og * tanhf_(c1[r]);
            }
        }
        barg(bid);
        if (act) {
#pragma unroll
            for (int r = 0; r < RPG; r++) HS1[r*HPAD + u] = hn[r];
        }
        barg(bid);

        // ================= layer 2 ================= (merged dual acc)
        if (act) {
#pragma unroll
            for (int r = 0; r < RPG; r++) { z[r].a = b2a; z[r].b = b2b; }
            acc50x2(z, W2, HS1, W2 + 50*200, HS2, u);
#pragma unroll
            for (int r = 0; r < RPG; r++) {
                float zi, zf, zg, zo;
                unpack2(z[r].a, zi, zf);
                unpack2(z[r].b, zg, zo);
                const float ig = sigmoidf_(zi);
                const float fg = sigmoidf_(zf);
                const float gg = tanhf_(zg);
                const float og = sigmoidf_(zo);
                c2[r] = fg * c2[r] + ig * gg;
                hn[r] = og * tanhf_(c2[r]);
            }
        }
        barg(bid);
        if (act) {
#pragma unroll
            for (int r = 0; r < RPG; r++) HS2[r*HPAD + u] = hn[r];
        }
        // x tile for t+1 loaded in the same write window (XS is group-private;
        // XS(t) was last read in this step's layer 0)
        if (t + 1 < Tn && gtid < RPG*Fn)
            XSg[gtid] = xb[xrow*(Tn*Fn) + (t+1)*Fn + xcol];
        barg(bid);
    }

    __syncthreads();

    // ---- final linear: out[b] = h2[b] . Wlin + blin ----
    if (tid < BC) {
        float s = blin[0];
#pragma unroll 10
        for (int uu = 0; uu < Hn; uu++)
            s += HS[2*(BC*HPAD) + tid*HPAD + uu] * Wlin[uu];
        out[bbase + tid] = s;
    }
}

extern "C" void kernel_launch(void* const* d_in, const int* in_sizes, int n_in,
                              void* d_out, int out_size)
{
    (void)in_sizes; (void)n_in; (void)out_size;
    const float* x    = (const float*)d_in[0];
    const float* Wih0 = (const float*)d_in[1];
    const float* Whh0 = (const float*)d_in[2];
    const float* bih0 = (const float*)d_in[3];
    const float* bhh0 = (const float*)d_in[4];
    const float* Wih1 = (const float*)d_in[5];
    const float* Whh1 = (const float*)d_in[6];
    const float* bih1 = (const float*)d_in[7];
    const float* bhh1 = (const float*)d_in[8];
    const float* Wih2 = (const float*)d_in[9];
    const float* Whh2 = (const float*)d_in[10];
    const float* bih2 = (const float*)d_in[11];
    const float* bhh2 = (const float*)d_in[12];
    const float* Wlin = (const float*)d_in[13];
    const float* blin = (const float*)d_in[14];
    float* out = (float*)d_out;

    cudaFuncSetAttribute(lstm_fused, cudaFuncAttributeMaxDynamicSharedMemorySize, SMEM_BYTES);
    lstm_fused<<<Bn / BC, NTHREADS, SMEM_BYTES>>>(
        x, Wih0, Whh0, bih0, bhh0,
        Wih1, Whh1, bih1, bhh1,
        Wih2, Whh2, bih2, bhh2,
        Wlin, blin, out);
}

// round 14
// speedup vs baseline: 1.3232x; 1.0014x over previous
#include <cuda_runtime.h>

// Problem constants
#define Tn 336
#define Fn 12
#define Hn 50
#define Bn 4096
#define BC 32          // batch rows per CTA
#define NTHREADS 512
#define HPAD 52        // h row stride (float4-aligned)
#define RPG 4          // rows per group (8 groups x 2 warps)

// shared memory float offsets
#define W0_OFF 0                 // layer0 combined [62][50][4]  = 12400 floats
#define W1_OFF 12400             // layer1 combined [100][50][4] = 20000
#define W2_OFF 32400             // layer2 combined [100][50][4] = 20000
#define HS_OFF 52400             // h state  3 * 32 * 52 = 4992
#define XS_OFF 57392             // x tile   32 * 12 = 384
#define SMEM_FLOATS 57776
#define SMEM_BYTES (SMEM_FLOATS * 4)

typedef unsigned long long u64;

// packed dual-fp32 FMA (sm_103a FFMA2): z += w * h (elementwise on 2 lanes)
__device__ __forceinline__ void ffma2(u64& z, const u64 w, const u64 h) {
    asm("fma.rn.f32x2 %0, %1, %2, %0;" : "+l"(z) : "l"(w), "l"(h));
}
// broadcast a scalar into both halves of a b64
__device__ __forceinline__ u64 dup2(const float s) {
    u64 r; asm("mov.b64 %0, {%1, %1};" : "=l"(r) : "f"(s)); return r;
}
__device__ __forceinline__ u64 pack2(const float lo, const float hi) {
    u64 r; asm("mov.b64 %0, {%1, %2};" : "=l"(r) : "f"(lo), "f"(hi)); return r;
}
__device__ __forceinline__ void unpack2(const u64 v, float& lo, float& hi) {
    asm("mov.b64 {%0, %1}, %2;" : "=f"(lo), "=f"(hi) : "l"(v));
}

__device__ __forceinline__ float sigmoidf_(float v) {
    return 1.0f / (1.0f + __expf(-v));
}
// precise-enough tanh: 1 - 2/(1+e^{2x}); ~1e-7 rel err
__device__ __forceinline__ float tanhf_(float v) {
    const float e = __expf(2.0f * v);
    return 1.0f - 2.0f / (e + 1.0f);
}

// named barrier for a 2-warp group (ids 1..8; 0 reserved for __syncthreads)
__device__ __forceinline__ void barg(int id) {
    asm volatile("bar.sync %0, 64;" :: "r"(id) : "memory");
}

struct Z2 { u64 a, b; };   // a = gates (i,f), b = gates (g,o)

// layer-0 x part: 12 k's over the 12-long x rows (stride Fn), float4 loads
__device__ __forceinline__ void accX4(Z2 z[RPG], const float* __restrict__ Wb,
                                      const float* __restrict__ xr, int u)
{
#pragma unroll
    for (int jb = 0; jb < 12; jb += 4) {
        const ulonglong2 w0 = *(const ulonglong2*)(Wb + ((jb+0)*50 + u)*4);
        const ulonglong2 w1 = *(const ulonglong2*)(Wb + ((jb+1)*50 + u)*4);
        const ulonglong2 w2 = *(const ulonglong2*)(Wb + ((jb+2)*50 + u)*4);
        const ulonglong2 w3 = *(const ulonglong2*)(Wb + ((jb+3)*50 + u)*4);
#pragma unroll
        for (int r = 0; r < RPG; r++) {
            const float4 xv = *(const float4*)(xr + r*Fn + jb);
            const u64 x0 = dup2(xv.x);
            const u64 x1 = dup2(xv.y);
            const u64 x2 = dup2(xv.z);
            const u64 x3 = dup2(xv.w);
            ffma2(z[r].a, w0.x, x0); ffma2(z[r].b, w0.y, x0);
            ffma2(z[r].a, w1.x, x1); ffma2(z[r].b, w1.y, x1);
            ffma2(z[r].a, w2.x, x2); ffma2(z[r].b, w2.y, x2);
            ffma2(z[r].a, w3.x, x3); ffma2(z[r].b, w3.y, x3);
        }
    }
}

// z[r] += sum_{j<50} W[j][u][:] * h[r][j]
__device__ __forceinline__ void acc50(Z2 z[RPG], const float* __restrict__ Wb,
                                      const float* __restrict__ hb, int u)
{
#pragma unroll 1
    for (int jb = 0; jb < 48; jb += 4) {
        const ulonglong2 w0 = *(const ulonglong2*)(Wb + ((jb+0)*50 + u)*4);
        const ulonglong2 w1 = *(const ulonglong2*)(Wb + ((jb+1)*50 + u)*4);
        const ulonglong2 w2 = *(const ulonglong2*)(Wb + ((jb+2)*50 + u)*4);
        const ulonglong2 w3 = *(const ulonglong2*)(Wb + ((jb+3)*50 + u)*4);
#pragma unroll
        for (int r = 0; r < RPG; r++) {
            const float4 hv = *(const float4*)(hb + r*HPAD + jb);
            const u64 h0 = dup2(hv.x);
            const u64 h1 = dup2(hv.y);
            const u64 h2 = dup2(hv.z);
            const u64 h3 = dup2(hv.w);
            ffma2(z[r].a, w0.x, h0); ffma2(z[r].b, w0.y, h0);
            ffma2(z[r].a, w1.x, h1); ffma2(z[r].b, w1.y, h1);
            ffma2(z[r].a, w2.x, h2); ffma2(z[r].b, w2.y, h2);
            ffma2(z[r].a, w3.x, h3); ffma2(z[r].b, w3.y, h3);
        }
    }
    const ulonglong2 w48 = *(const ulonglong2*)(Wb + (48*50 + u)*4);
    const ulonglong2 w49 = *(const ulonglong2*)(Wb + (49*50 + u)*4);
#pragma unroll
    for (int r = 0; r < RPG; r++) {
        const u64 h48 = dup2(hb[r*HPAD + 48]);
        const u64 h49 = dup2(hb[r*HPAD + 49]);
        ffma2(z[r].a, w48.x, h48); ffma2(z[r].b, w48.y, h48);
        ffma2(z[r].a, w49.x, h49); ffma2(z[r].b, w49.y, h49);
    }
}

// merged double accumulation: z += Wa.h_a + Wb.h_b in one loop (2x ILP per iter)
__device__ __forceinline__ void acc50x2(Z2 z[RPG],
                                        const float* __restrict__ Wa,
                                        const float* __restrict__ ha,
                                        const float* __restrict__ Wb,
                                        const float* __restrict__ hb, int u)
{
#pragma unroll 1
    for (int jb = 0; jb < 48; jb += 4) {
        const ulonglong2 a0 = *(const ulonglong2*)(Wa + ((jb+0)*50 + u)*4);
        const ulonglong2 a1 = *(const ulonglong2*)(Wa + ((jb+1)*50 + u)*4);
        const ulonglong2 a2 = *(const ulonglong2*)(Wa + ((jb+2)*50 + u)*4);
        const ulonglong2 a3 = *(const ulonglong2*)(Wa + ((jb+3)*50 + u)*4);
        const ulonglong2 b0 = *(const ulonglong2*)(Wb + ((jb+0)*50 + u)*4);
        const ulonglong2 b1 = *(const ulonglong2*)(Wb + ((jb+1)*50 + u)*4);
        const ulonglong2 b2 = *(const ulonglong2*)(Wb + ((jb+2)*50 + u)*4);
        const ulonglong2 b3 = *(const ulonglong2*)(Wb + ((jb+3)*50 + u)*4);
#pragma unroll
        for (int r = 0; r < RPG; r++) {
            const float4 hva = *(const float4*)(ha + r*HPAD + jb);
            const float4 hvb = *(const float4*)(hb + r*HPAD + jb);
            const u64 ha0 = dup2(hva.x);
            const u64 ha1 = dup2(hva.y);
            const u64 ha2 = dup2(hva.z);
            const u64 ha3 = dup2(hva.w);
            ffma2(z[r].a, a0.x, ha0); ffma2(z[r].b, a0.y, ha0);
            ffma2(z[r].a, a1.x, ha1); ffma2(z[r].b, a1.y, ha1);
            ffma2(z[r].a, a2.x, ha2); ffma2(z[r].b, a2.y, ha2);
            ffma2(z[r].a, a3.x, ha3); ffma2(z[r].b, a3.y, ha3);
            const u64 hb0 = dup2(hvb.x);
            const u64 hb1 = dup2(hvb.y);
            const u64 hb2 = dup2(hvb.z);
            const u64 hb3 = dup2(hvb.w);
            ffma2(z[r].a, b0.x, hb0); ffma2(z[r].b, b0.y, hb0);
            ffma2(z[r].a, b1.x, hb1); ffma2(z[r].b, b1.y, hb1);
            ffma2(z[r].a, b2.x, hb2); ffma2(z[r].b, b2.y, hb2);
            ffma2(z[r].a, b3.x, hb3); ffma2(z[r].b, b3.y, hb3);
        }
    }
    const ulonglong2 a48 = *(const ulonglong2*)(Wa + (48*50 + u)*4);
    const ulonglong2 a49 = *(const ulonglong2*)(Wa + (49*50 + u)*4);
    const ulonglong2 b48 = *(const ulonglong2*)(Wb + (48*50 + u)*4);
    const ulonglong2 b49 = *(const ulonglong2*)(Wb + (49*50 + u)*4);
#pragma unroll
    for (int r = 0; r < RPG; r++) {
        const u64 ha48 = dup2(ha[r*HPAD + 48]);
        const u64 ha49 = dup2(ha[r*HPAD + 49]);
        const u64 hb48 = dup2(hb[r*HPAD + 48]);
        const u64 hb49 = dup2(hb[r*HPAD + 49]);
        ffma2(z[r].a, a48.x, ha48); ffma2(z[r].b, a48.y, ha48);
        ffma2(z[r].a, a49.x, ha49); ffma2(z[r].b, a49.y, ha49);
        ffma2(z[r].a, b48.x, hb48); ffma2(z[r].b, b48.y, hb48);
        ffma2(z[r].a, b49.x, hb49); ffma2(z[r].b, b49.y, hb49);
    }
}

__global__ void __launch_bounds__(NTHREADS, 1)
lstm_fused(const float* __restrict__ x,
           const float* __restrict__ Wih0, const float* __restrict__ Whh0,
           const float* __restrict__ bih0, const float* __restrict__ bhh0,
           const float* __restrict__ Wih1, const float* __restrict__ Whh1,
           const float* __restrict__ bih1, const float* __restrict__ bhh1,
           const float* __restrict__ Wih2, const float* __restrict__ Whh2,
           const float* __restrict__ bih2, const float* __restrict__ bhh2,
           const float* __restrict__ Wlin, const float* __restrict__ blin,
           float* __restrict__ out)
{
    extern __shared__ float sm[];
    float* W0 = sm + W0_OFF;
    float* W1 = sm + W1_OFF;
    float* W2 = sm + W2_OFF;
    float* HS = sm + HS_OFF;   // [3][BC][HPAD]
    float* XS = sm + XS_OFF;   // [BC][12]

    const int tid   = threadIdx.x;
    const int lane  = tid & 31;
    const int wid   = tid >> 5;
    const int grp   = wid >> 1;               // 0..7
    const int bid   = grp + 1;                // named barrier id
    const int r0    = grp * RPG;              // row base (4 rows)
    const int u     = (wid & 1) * 32 + lane;  // unit id
    const bool act  = (u < Hn);
    const int gtid  = tid & 63;               // thread id within group

    // ---- stage weights into shared with [k][u][gate] layout ----
    for (int idx = tid; idx < 12400; idx += NTHREADS) {
        const int g  = idx & 3;
        const int uu = (idx >> 2) % 50;
        const int k  = idx / 200;
        W0[idx] = (k < 12) ? Wih0[(g*50 + uu)*12 + k]
                           : Whh0[(g*50 + uu)*50 + (k - 12)];
    }
    for (int idx = tid; idx < 20000; idx += NTHREADS) {
        const int g  = idx & 3;
        const int uu = (idx >> 2) % 50;
        const int k  = idx / 200;
        W1[idx] = (k < 50) ? Wih1[(g*50 + uu)*50 + k]
                           : Whh1[(g*50 + uu)*50 + (k - 50)];
    }
    for (int idx = tid; idx < 20000; idx += NTHREADS) {
        const int g  = idx & 3;
        const int uu = (idx >> 2) % 50;
        const int k  = idx / 200;
        W2[idx] = (k < 50) ? Wih2[(g*50 + uu)*50 + k]
                           : Whh2[(g*50 + uu)*50 + (k - 50)];
    }
    for (int idx = tid; idx < 3*BC*HPAD; idx += NTHREADS) HS[idx] = 0.0f;

    u64 b0a = 0, b0b = 0, b1a = 0, b1b = 0, b2a = 0, b2b = 0;
    if (act) {
        b0a = pack2(bih0[u]       + bhh0[u],       bih0[50 + u]  + bhh0[50 + u]);
        b0b = pack2(bih0[100 + u] + bhh0[100 + u], bih0[150 + u] + bhh0[150 + u]);
        b1a = pack2(bih1[u]       + bhh1[u],       bih1[50 + u]  + bhh1[50 + u]);
        b1b = pack2(bih1[100 + u] + bhh1[100 + u], bih1[150 + u] + bhh1[150 + u]);
        b2a = pack2(bih2[u]       + bhh2[u],       bih2[50 + u]  + bhh2[50 + u]);
        b2b = pack2(bih2[100 + u] + bhh2[100 + u], bih2[150 + u] + bhh2[150 + u]);
    }

    float c0[RPG], c1[RPG], c2[RPG];
#pragma unroll
    for (int r = 0; r < RPG; r++) { c0[r] = 0.f; c1[r] = 0.f; c2[r] = 0.f; }

    const long long bbase = (long long)blockIdx.x * BC;
    const float* xb = x + bbase * (Tn * Fn);

    const int xrow = r0 + gtid / Fn;          // valid if gtid < 48
    const int xcol = gtid % Fn;

    float* HS0 = HS + 0*(BC*HPAD) + r0*HPAD;
    float* HS1 = HS + 1*(BC*HPAD) + r0*HPAD;
    float* HS2 = HS + 2*(BC*HPAD) + r0*HPAD;
    float* XSg = XS + r0*Fn;

    // prime x tile for t=0 (covered by the __syncthreads below)
    if (gtid < RPG*Fn)
        XSg[gtid] = xb[xrow*(Tn*Fn) + 0*Fn + xcol];

    __syncthreads();

    for (int t = 0; t < Tn; t++) {
        float hn[RPG];
        Z2 z[RPG];

        // ================= layer 0 ================= (XS(t) ready from prev iter)
        if (act) {
#pragma unroll
            for (int r = 0; r < RPG; r++) { z[r].a = b0a; z[r].b = b0b; }
            accX4(z, W0, XSg, u);
            acc50(z, W0 + 12*200, HS0, u);
#pragma unroll
            for (int r = 0; r < RPG; r++) {
                float zi, zf, zg, zo;
                unpack2(z[r].a, zi, zf);
                unpack2(z[r].b, zg, zo);
                const float ig = sigmoidf_(zi);
                const float fg = sigmoidf_(zf);
                const float gg = tanhf_(zg);
                const float og = sigmoidf_(zo);
                c0[r] = fg * c0[r] + ig * gg;
                hn[r] = og * tanhf_(c0[r]);
            }
        }
        barg(bid);
        if (act) {
#pragma unroll
            for (int r = 0; r < RPG; r++) HS0[r*HPAD + u] = hn[r];
        }
        barg(bid);

        // ================= layer 1 ================= (merged dual acc)
        if (act) {
#pragma unroll
            for (int r = 0; r < RPG; r++) { z[r].a = b1a; z[r].b = b1b; }
            acc50x2(z, W1, HS0, W1 + 50*200, HS1, u);
#pragma unroll
            for (int r = 0; r < RPG; r++) {
                float zi, zf, zg, zo;
                unpack2(z[r].a, zi, zf);
                unpack2(z[r].b, zg, zo);
                const float ig = sigmoidf_(zi);
                const float fg = sigmoidf_(zf);
                const float gg = tanhf_(zg);
                const float og = sigmoidf_(zo);
                c1[r] = fg * c1[r] + ig * gg;
                hn[r] = og * tanhf_(c1[r]);
            }
        }
        barg(bid);
        if (act) {
#pragma unroll
            for (int r = 0; r < RPG; r++) HS1[r*HPAD + u] = hn[r];
        }
        barg(bid);

        // ================= layer 2 ================= (merged dual acc)
        if (act) {
#pragma unroll
            for (int r = 0; r < RPG; r++) { z[r].a = b2a; z[r].b = b2b; }
            acc50x2(z, W2, HS1, W2 + 50*200, HS2, u);
#pragma unroll
            for (int r = 0; r < RPG; r++) {
                float zi, zf, zg, zo;
                unpack2(z[r].a, zi, zf);
                unpack2(z[r].b, zg, zo);
                const float ig = sigmoidf_(zi);
                const float fg = sigmoidf_(zf);
                const float gg = tanhf_(zg);
                const float og = sigmoidf_(zo);
                c2[r] = fg * c2[r] + ig * gg;
                hn[r] = og * tanhf_(c2[r]);
            }
        }
        barg(bid);
        if (act) {
#pragma unroll
            for (int r = 0; r < RPG; r++) HS2[r*HPAD + u] = hn[r];
        }
        // x tile for t+1 loaded in the same write window (XS is group-private;
        // XS(t) was last read in this step's layer 0)
        if (t + 1 < Tn && gtid < RPG*Fn)
            XSg[gtid] = xb[xrow*(Tn*Fn) + (t+1)*Fn + xcol];
        barg(bid);
    }

    __syncthreads();

    // ---- final linear: out[b] = h2[b] . Wlin + blin ----
    if (tid < BC) {
        float s = blin[0];
#pragma unroll 10
        for (int uu = 0; uu < Hn; uu++)
            s += HS[2*(BC*HPAD) + tid*HPAD + uu] * Wlin[uu];
        out[bbase + tid] = s;
    }
}

extern "C" void kernel_launch(void* const* d_in, const int* in_sizes, int n_in,
                              void* d_out, int out_size)
{
    (void)in_sizes; (void)n_in; (void)out_size;
    const float* x    = (const float*)d_in[0];
    const float* Wih0 = (const float*)d_in[1];
    const float* Whh0 = (const float*)d_in[2];
    const float* bih0 = (const float*)d_in[3];
    const float* bhh0 = (const float*)d_in[4];
    const float* Wih1 = (const float*)d_in[5];
    const float* Whh1 = (const float*)d_in[6];
    const float* bih1 = (const float*)d_in[7];
    const float* bhh1 = (const float*)d_in[8];
    const float* Wih2 = (const float*)d_in[9];
    const float* Whh2 = (const float*)d_in[10];
    const float* bih2 = (const float*)d_in[11];
    const float* bhh2 = (const float*)d_in[12];
    const float* Wlin = (const float*)d_in[13];
    const float* blin = (const float*)d_in[14];
    float* out = (float*)d_out;

    cudaFuncSetAttribute(lstm_fused, cudaFuncAttributeMaxDynamicSharedMemorySize, SMEM_BYTES);
    lstm_fused<<<Bn / BC, NTHREADS, SMEM_BYTES>>>(
        x, Wih0, Whh0, bih0, bhh0,
        Wih1, Whh1, bih1, bhh1,
        Wih2, Whh2, bih2, bhh2,
        Wlin, blin, out);
}

// round 15
// speedup vs baseline: 1.3332x; 1.0076x over previous
#include <cuda_runtime.h>

// Problem constants
#define Tn 336
#define Fn 12
#define Hn 50
#define Bn 4096
#define BC 32          // batch rows per CTA
#define NTHREADS 512
#define HPAD 52        // h row stride (float4-aligned)
#define RPG 4          // rows per group (8 groups x 2 warps)

// shared memory float offsets
#define W0_OFF 0                 // layer0 combined [62][50][4]  = 12400 floats
#define W1_OFF 12400             // layer1 combined [100][50][4] = 20000
#define W2_OFF 32400             // layer2 combined [100][50][4] = 20000
#define HS_OFF 52400             // h state  3 * 32 * 52 = 4992
#define XS_OFF 57392             // x tile   32 * 12 = 384
#define SMEM_FLOATS 57776
#define SMEM_BYTES (SMEM_FLOATS * 4)

typedef unsigned long long u64;

// packed dual-fp32 FMA (sm_103a FFMA2): z += w * h (elementwise on 2 lanes)
__device__ __forceinline__ void ffma2(u64& z, const u64 w, const u64 h) {
    asm("fma.rn.f32x2 %0, %1, %2, %0;" : "+l"(z) : "l"(w), "l"(h));
}
// broadcast a scalar into both halves of a b64
__device__ __forceinline__ u64 dup2(const float s) {
    u64 r; asm("mov.b64 %0, {%1, %1};" : "=l"(r) : "f"(s)); return r;
}
__device__ __forceinline__ u64 pack2(const float lo, const float hi) {
    u64 r; asm("mov.b64 %0, {%1, %2};" : "=l"(r) : "f"(lo), "f"(hi)); return r;
}
__device__ __forceinline__ void unpack2(const u64 v, float& lo, float& hi) {
    asm("mov.b64 {%0, %1}, %2;" : "=f"(lo), "=f"(hi) : "l"(v));
}

__device__ __forceinline__ float sigmoidf_(float v) {
    return 1.0f / (1.0f + __expf(-v));
}
// precise-enough tanh: 1 - 2/(1+e^{2x}); ~1e-7 rel err
__device__ __forceinline__ float tanhf_(float v) {
    const float e = __expf(2.0f * v);
    return 1.0f - 2.0f / (e + 1.0f);
}

// named barrier for a 2-warp group (ids 1..8; 0 reserved for __syncthreads)
__device__ __forceinline__ void barg(int id) {
    asm volatile("bar.sync %0, 64;" :: "r"(id) : "memory");
}

struct Z2 { u64 a, b; };   // a = gates (i,f), b = gates (g,o)

// layer-0 x part: 12 k's over the 12-long x rows (stride Fn), float4 loads
__device__ __forceinline__ void accX4(Z2 z[RPG], const float* __restrict__ Wb,
                                      const float* __restrict__ xr, int u)
{
#pragma unroll
    for (int jb = 0; jb < 12; jb += 4) {
        const ulonglong2 w0 = *(const ulonglong2*)(Wb + ((jb+0)*50 + u)*4);
        const ulonglong2 w1 = *(const ulonglong2*)(Wb + ((jb+1)*50 + u)*4);
        const ulonglong2 w2 = *(const ulonglong2*)(Wb + ((jb+2)*50 + u)*4);
        const ulonglong2 w3 = *(const ulonglong2*)(Wb + ((jb+3)*50 + u)*4);
#pragma unroll
        for (int r = 0; r < RPG; r++) {
            const float4 xv = *(const float4*)(xr + r*Fn + jb);
            const u64 x0 = dup2(xv.x);
            const u64 x1 = dup2(xv.y);
            const u64 x2 = dup2(xv.z);
            const u64 x3 = dup2(xv.w);
            ffma2(z[r].a, w0.x, x0); ffma2(z[r].b, w0.y, x0);
            ffma2(z[r].a, w1.x, x1); ffma2(z[r].b, w1.y, x1);
            ffma2(z[r].a, w2.x, x2); ffma2(z[r].b, w2.y, x2);
            ffma2(z[r].a, w3.x, x3); ffma2(z[r].b, w3.y, x3);
        }
    }
}

// z[r] += sum_{j<50} W[j][u][:] * h[r][j]
__device__ __forceinline__ void acc50(Z2 z[RPG], const float* __restrict__ Wb,
                                      const float* __restrict__ hb, int u)
{
#pragma unroll 1
    for (int jb = 0; jb < 48; jb += 4) {
        const ulonglong2 w0 = *(const ulonglong2*)(Wb + ((jb+0)*50 + u)*4);
        const ulonglong2 w1 = *(const ulonglong2*)(Wb + ((jb+1)*50 + u)*4);
        const ulonglong2 w2 = *(const ulonglong2*)(Wb + ((jb+2)*50 + u)*4);
        const ulonglong2 w3 = *(const ulonglong2*)(Wb + ((jb+3)*50 + u)*4);
#pragma unroll
        for (int r = 0; r < RPG; r++) {
            const float4 hv = *(const float4*)(hb + r*HPAD + jb);
            const u64 h0 = dup2(hv.x);
            const u64 h1 = dup2(hv.y);
            const u64 h2 = dup2(hv.z);
            const u64 h3 = dup2(hv.w);
            ffma2(z[r].a, w0.x, h0); ffma2(z[r].b, w0.y, h0);
            ffma2(z[r].a, w1.x, h1); ffma2(z[r].b, w1.y, h1);
            ffma2(z[r].a, w2.x, h2); ffma2(z[r].b, w2.y, h2);
            ffma2(z[r].a, w3.x, h3); ffma2(z[r].b, w3.y, h3);
        }
    }
    const ulonglong2 w48 = *(const ulonglong2*)(Wb + (48*50 + u)*4);
    const ulonglong2 w49 = *(const ulonglong2*)(Wb + (49*50 + u)*4);
#pragma unroll
    for (int r = 0; r < RPG; r++) {
        const u64 h48 = dup2(hb[r*HPAD + 48]);
        const u64 h49 = dup2(hb[r*HPAD + 49]);
        ffma2(z[r].a, w48.x, h48); ffma2(z[r].b, w48.y, h48);
        ffma2(z[r].a, w49.x, h49); ffma2(z[r].b, w49.y, h49);
    }
}

// merged double accumulation: z += Wa.h_a + Wb.h_b in one loop (2x ILP per iter)
__device__ __forceinline__ void acc50x2(Z2 z[RPG],
                                        const float* __restrict__ Wa,
                                        const float* __restrict__ ha,
                                        const float* __restrict__ Wb,
                                        const float* __restrict__ hb, int u)
{
#pragma unroll 1
    for (int jb = 0; jb < 48; jb += 4) {
        const ulonglong2 a0 = *(const ulonglong2*)(Wa + ((jb+0)*50 + u)*4);
        const ulonglong2 a1 = *(const ulonglong2*)(Wa + ((jb+1)*50 + u)*4);
        const ulonglong2 a2 = *(const ulonglong2*)(Wa + ((jb+2)*50 + u)*4);
        const ulonglong2 a3 = *(const ulonglong2*)(Wa + ((jb+3)*50 + u)*4);
        const ulonglong2 b0 = *(const ulonglong2*)(Wb + ((jb+0)*50 + u)*4);
        const ulonglong2 b1 = *(const ulonglong2*)(Wb + ((jb+1)*50 + u)*4);
        const ulonglong2 b2 = *(const ulonglong2*)(Wb + ((jb+2)*50 + u)*4);
        const ulonglong2 b3 = *(const ulonglong2*)(Wb + ((jb+3)*50 + u)*4);
#pragma unroll
        for (int r = 0; r < RPG; r++) {
            const float4 hva = *(const float4*)(ha + r*HPAD + jb);
            const float4 hvb = *(const float4*)(hb + r*HPAD + jb);
            const u64 ha0 = dup2(hva.x);
            const u64 ha1 = dup2(hva.y);
            const u64 ha2 = dup2(hva.z);
            const u64 ha3 = dup2(hva.w);
            ffma2(z[r].a, a0.x, ha0); ffma2(z[r].b, a0.y, ha0);
            ffma2(z[r].a, a1.x, ha1); ffma2(z[r].b, a1.y, ha1);
            ffma2(z[r].a, a2.x, ha2); ffma2(z[r].b, a2.y, ha2);
            ffma2(z[r].a, a3.x, ha3); ffma2(z[r].b, a3.y, ha3);
            const u64 hb0 = dup2(hvb.x);
            const u64 hb1 = dup2(hvb.y);
            const u64 hb2 = dup2(hvb.z);
            const u64 hb3 = dup2(hvb.w);
            ffma2(z[r].a, b0.x, hb0); ffma2(z[r].b, b0.y, hb0);
            ffma2(z[r].a, b1.x, hb1); ffma2(z[r].b, b1.y, hb1);
            ffma2(z[r].a, b2.x, hb2); ffma2(z[r].b, b2.y, hb2);
            ffma2(z[r].a, b3.x, hb3); ffma2(z[r].b, b3.y, hb3);
        }
    }
    const ulonglong2 a48 = *(const ulonglong2*)(Wa + (48*50 + u)*4);
    const ulonglong2 a49 = *(const ulonglong2*)(Wa + (49*50 + u)*4);
    const ulonglong2 b48 = *(const ulonglong2*)(Wb + (48*50 + u)*4);
    const ulonglong2 b49 = *(const ulonglong2*)(Wb + (49*50 + u)*4);
#pragma unroll
    for (int r = 0; r < RPG; r++) {
        const u64 ha48 = dup2(ha[r*HPAD + 48]);
        const u64 ha49 = dup2(ha[r*HPAD + 49]);
        const u64 hb48 = dup2(hb[r*HPAD + 48]);
        const u64 hb49 = dup2(hb[r*HPAD + 49]);
        ffma2(z[r].a, a48.x, ha48); ffma2(z[r].b, a48.y, ha48);
        ffma2(z[r].a, a49.x, ha49); ffma2(z[r].b, a49.y, ha49);
        ffma2(z[r].a, b48.x, hb48); ffma2(z[r].b, b48.y, hb48);
        ffma2(z[r].a, b49.x, hb49); ffma2(z[r].b, b49.y, hb49);
    }
}

__global__ void __launch_bounds__(NTHREADS, 1)
lstm_fused(const float* __restrict__ x,
           const float* __restrict__ Wih0, const float* __restrict__ Whh0,
           const float* __restrict__ bih0, const float* __restrict__ bhh0,
           const float* __restrict__ Wih1, const float* __restrict__ Whh1,
           const float* __restrict__ bih1, const float* __restrict__ bhh1,
           const float* __restrict__ Wih2, const float* __restrict__ Whh2,
           const float* __restrict__ bih2, const float* __restrict__ bhh2,
           const float* __restrict__ Wlin, const float* __restrict__ blin,
           float* __restrict__ out)
{
    extern __shared__ float sm[];
    float* W0 = sm + W0_OFF;
    float* W1 = sm + W1_OFF;
    float* W2 = sm + W2_OFF;
    float* HS = sm + HS_OFF;   // [3][BC][HPAD]
    float* XS = sm + XS_OFF;   // [BC][12]

    const int tid   = threadIdx.x;
    const int lane  = tid & 31;
    const int wid   = tid >> 5;
    const int grp   = wid >> 1;               // 0..7
    const int bid   = grp + 1;                // named barrier id
    const int r0    = grp * RPG;              // row base (4 rows)
    const int u     = (wid & 1) * 32 + lane;  // unit id
    const bool act  = (u < Hn);
    const int gtid  = tid & 63;               // thread id within group

    // ---- stage weights into shared with [k][u][gate] layout ----
    for (int idx = tid; idx < 12400; idx += NTHREADS) {
        const int g  = idx & 3;
        const int uu = (idx >> 2) % 50;
        const int k  = idx / 200;
        W0[idx] = (k < 12) ? Wih0[(g*50 + uu)*12 + k]
                           : Whh0[(g*50 + uu)*50 + (k - 12)];
    }
    for (int idx = tid; idx < 20000; idx += NTHREADS) {
        const int g  = idx & 3;
        const int uu = (idx >> 2) % 50;
        const int k  = idx / 200;
        W1[idx] = (k < 50) ? Wih1[(g*50 + uu)*50 + k]
                           : Whh1[(g*50 + uu)*50 + (k - 50)];
    }
    for (int idx = tid; idx < 20000; idx += NTHREADS) {
        const int g  = idx & 3;
        const int uu = (idx >> 2) % 50;
        const int k  = idx / 200;
        W2[idx] = (k < 50) ? Wih2[(g*50 + uu)*50 + k]
                           : Whh2[(g*50 + uu)*50 + (k - 50)];
    }
    for (int idx = tid; idx < 3*BC*HPAD; idx += NTHREADS) HS[idx] = 0.0f;

    u64 b0a = 0, b0b = 0, b1a = 0, b1b = 0, b2a = 0, b2b = 0;
    if (act) {
        b0a = pack2(bih0[u]       + bhh0[u],       bih0[50 + u]  + bhh0[50 + u]);
        b0b = pack2(bih0[100 + u] + bhh0[100 + u], bih0[150 + u] + bhh0[150 + u]);
        b1a = pack2(bih1[u]       + bhh1[u],       bih1[50 + u]  + bhh1[50 + u]);
        b1b = pack2(bih1[100 + u] + bhh1[100 + u], bih1[150 + u] + bhh1[150 + u]);
        b2a = pack2(bih2[u]       + bhh2[u],       bih2[50 + u]  + bhh2[50 + u]);
        b2b = pack2(bih2[100 + u] + bhh2[100 + u], bih2[150 + u] + bhh2[150 + u]);
    }

    float c0[RPG], c1[RPG], c2[RPG];
#pragma unroll
    for (int r = 0; r < RPG; r++) { c0[r] = 0.f; c1[r] = 0.f; c2[r] = 0.f; }

    const long long bbase = (long long)blockIdx.x * BC;
    const float* xb = x + bbase * (Tn * Fn);

    const int xrow = r0 + gtid / Fn;          // valid if gtid < 48
    const int xcol = gtid % Fn;

    float* HS0 = HS + 0*(BC*HPAD) + r0*HPAD;
    float* HS1 = HS + 1*(BC*HPAD) + r0*HPAD;
    float* HS2 = HS + 2*(BC*HPAD) + r0*HPAD;
    float* XSg = XS + r0*Fn;

    // prime x tile for phase 0 (covered by the __syncthreads below)
    if (gtid < RPG*Fn)
        XSg[gtid] = xb[xrow*(Tn*Fn) + 0*Fn + xcol];

    __syncthreads();

    // ===== skewed layer pipeline: phase p computes l0(p), l1(p-1), l2(p-2) =====
    // All reads are one phase-generation old; all writes in the write window.
    for (int p = 0; p < Tn + 2; p++) {
        const bool L0 = (p < Tn);
        const bool L1 = (p >= 1) && (p <= Tn);
        const bool L2 = (p >= 2);
        float hn0[RPG], hn1[RPG], hn2[RPG];
        Z2 z[RPG];

        if (act) {
            // ---- layer 0, time p ----
            if (L0) {
#pragma unroll
                for (int r = 0; r < RPG; r++) { z[r].a = b0a; z[r].b = b0b; }
                accX4(z, W0, XSg, u);
                acc50(z, W0 + 12*200, HS0, u);
#pragma unroll
                for (int r = 0; r < RPG; r++) {
                    float zi, zf, zg, zo;
                    unpack2(z[r].a, zi, zf);
                    unpack2(z[r].b, zg, zo);
                    const float ig = sigmoidf_(zi);
                    const float fg = sigmoidf_(zf);
                    const float gg = tanhf_(zg);
                    const float og = sigmoidf_(zo);
                    c0[r] = fg * c0[r] + ig * gg;
                    hn0[r] = og * tanhf_(c0[r]);
                }
            }
            // ---- layer 1, time p-1 ----
            if (L1) {
#pragma unroll
                for (int r = 0; r < RPG; r++) { z[r].a = b1a; z[r].b = b1b; }
                acc50x2(z, W1, HS0, W1 + 50*200, HS1, u);
#pragma unroll
                for (int r = 0; r < RPG; r++) {
                    float zi, zf, zg, zo;
                    unpack2(z[r].a, zi, zf);
                    unpack2(z[r].b, zg, zo);
                    const float ig = sigmoidf_(zi);
                    const float fg = sigmoidf_(zf);
                    const float gg = tanhf_(zg);
                    const float og = sigmoidf_(zo);
                    c1[r] = fg * c1[r] + ig * gg;
                    hn1[r] = og * tanhf_(c1[r]);
                }
            }
            // ---- layer 2, time p-2 ----
            if (L2) {
#pragma unroll
                for (int r = 0; r < RPG; r++) { z[r].a = b2a; z[r].b = b2b; }
                acc50x2(z, W2, HS1, W2 + 50*200, HS2, u);
#pragma unroll
                for (int r = 0; r < RPG; r++) {
                    float zi, zf, zg, zo;
                    unpack2(z[r].a, zi, zf);
                    unpack2(z[r].b, zg, zo);
                    const float ig = sigmoidf_(zi);
                    const float fg = sigmoidf_(zf);
                    const float gg = tanhf_(zg);
                    const float og = sigmoidf_(zo);
                    c2[r] = fg * c2[r] + ig * gg;
                    hn2[r] = og * tanhf_(c2[r]);
                }
            }
        }
        barg(bid);
        if (act) {
            if (L0) {
#pragma unroll
                for (int r = 0; r < RPG; r++) HS0[r*HPAD + u] = hn0[r];
            }
            if (L1) {
#pragma unroll
                for (int r = 0; r < RPG; r++) HS1[r*HPAD + u] = hn1[r];
            }
            if (L2) {
#pragma unroll
                for (int r = 0; r < RPG; r++) HS2[r*HPAD + u] = hn2[r];
            }
        }
        // x tile for phase p+1 (XS group-private; XS(p) last read this phase)
        if (p + 1 < Tn && gtid < RPG*Fn)
            XSg[gtid] = xb[xrow*(Tn*Fn) + (p+1)*Fn + xcol];
        barg(bid);
    }

    __syncthreads();

    // ---- final linear: out[b] = h2[b] . Wlin + blin ----
    if (tid < BC) {
        float s = blin[0];
#pragma unroll 10
        for (int uu = 0; uu < Hn; uu++)
            s += HS[2*(BC*HPAD) + tid*HPAD + uu] * Wlin[uu];
        out[bbase + tid] = s;
    }
}

extern "C" void kernel_launch(void* const* d_in, const int* in_sizes, int n_in,
                              void* d_out, int out_size)
{
    (void)in_sizes; (void)n_in; (void)out_size;
    const float* x    = (const float*)d_in[0];
    const float* Wih0 = (const float*)d_in[1];
    const float* Whh0 = (const float*)d_in[2];
    const float* bih0 = (const float*)d_in[3];
    const float* bhh0 = (const float*)d_in[4];
    const float* Wih1 = (const float*)d_in[5];
    const float* Whh1 = (const float*)d_in[6];
    const float* bih1 = (const float*)d_in[7];
    const float* bhh1 = (const float*)d_in[8];
    const float* Wih2 = (const float*)d_in[9];
    const float* Whh2 = (const float*)d_in[10];
    const float* bih2 = (const float*)d_in[11];
    const float* bhh2 = (const float*)d_in[12];
    const float* Wlin = (const float*)d_in[13];
    const float* blin = (const float*)d_in[14];
    float* out = (float*)d_out;

    cudaFuncSetAttribute(lstm_fused, cudaFuncAttributeMaxDynamicSharedMemorySize, SMEM_BYTES);
    lstm_fused<<<Bn / BC, NTHREADS, SMEM_BYTES>>>(
        x, Wih0, Whh0, bih0, bhh0,
        Wih1, Whh1, bih1, bhh1,
        Wih2, Whh2, bih2, bhh2,
        Wlin, blin, out);
}

// round 16
// speedup vs baseline: 1.3568x; 1.0177x over previous
#include <cuda_runtime.h>

// Problem constants
#define Tn 336
#define Fn 12
#define Hn 50
#define Bn 4096
#define BC 32          // batch rows per CTA
#define NTHREADS 512
#define HPAD 52        // h row stride (float4-aligned)
#define RPG 4          // rows per group (8 groups x 2 warps)

// shared memory float offsets
#define W0_OFF 0                 // layer0 combined [62][50][4]  = 12400 floats
#define W1_OFF 12400             // layer1 combined [100][50][4] = 20000
#define W2_OFF 32400             // layer2 combined [100][50][4] = 20000
#define HS_OFF 52400             // h state  3 * 32 * 52 = 4992
#define XS_OFF 57392             // x tile   32 * 12 = 384
#define SMEM_FLOATS 57776
#define SMEM_BYTES (SMEM_FLOATS * 4)

typedef unsigned long long u64;

// packed dual-fp32 FMA (sm_103a FFMA2): z += w * h (elementwise on 2 lanes)
__device__ __forceinline__ void ffma2(u64& z, const u64 w, const u64 h) {
    asm("fma.rn.f32x2 %0, %1, %2, %0;" : "+l"(z) : "l"(w), "l"(h));
}
// broadcast a scalar into both halves of a b64
__device__ __forceinline__ u64 dup2(const float s) {
    u64 r; asm("mov.b64 %0, {%1, %1};" : "=l"(r) : "f"(s)); return r;
}
__device__ __forceinline__ u64 pack2(const float lo, const float hi) {
    u64 r; asm("mov.b64 %0, {%1, %2};" : "=l"(r) : "f"(lo), "f"(hi)); return r;
}
__device__ __forceinline__ void unpack2(const u64 v, float& lo, float& hi) {
    asm("mov.b64 {%0, %1}, %2;" : "=f"(lo), "=f"(hi) : "l"(v));
}

__device__ __forceinline__ float sigmoidf_(float v) {
    return 1.0f / (1.0f + __expf(-v));
}
// precise-enough tanh: 1 - 2/(1+e^{2x}); ~1e-7 rel err
__device__ __forceinline__ float tanhf_(float v) {
    const float e = __expf(2.0f * v);
    return 1.0f - 2.0f / (e + 1.0f);
}

// named barrier for a 2-warp group (ids 1..8; 0 reserved for __syncthreads)
__device__ __forceinline__ void barg(int id) {
    asm volatile("bar.sync %0, 64;" :: "r"(id) : "memory");
}

struct Z2 { u64 a, b; };   // a = gates (i,f), b = gates (g,o)

// layer-0 x part: 12 k's over the 12-long x rows (stride Fn), float4 loads
__device__ __forceinline__ void accX4(Z2 z[RPG], const float* __restrict__ Wb,
                                      const float* __restrict__ xr, int u)
{
#pragma unroll
    for (int jb = 0; jb < 12; jb += 4) {
        const ulonglong2 w0 = *(const ulonglong2*)(Wb + ((jb+0)*50 + u)*4);
        const ulonglong2 w1 = *(const ulonglong2*)(Wb + ((jb+1)*50 + u)*4);
        const ulonglong2 w2 = *(const ulonglong2*)(Wb + ((jb+2)*50 + u)*4);
        const ulonglong2 w3 = *(const ulonglong2*)(Wb + ((jb+3)*50 + u)*4);
#pragma unroll
        for (int r = 0; r < RPG; r++) {
            const float4 xv = *(const float4*)(xr + r*Fn + jb);
            const u64 x0 = dup2(xv.x);
            const u64 x1 = dup2(xv.y);
            const u64 x2 = dup2(xv.z);
            const u64 x3 = dup2(xv.w);
            ffma2(z[r].a, w0.x, x0); ffma2(z[r].b, w0.y, x0);
            ffma2(z[r].a, w1.x, x1); ffma2(z[r].b, w1.y, x1);
            ffma2(z[r].a, w2.x, x2); ffma2(z[r].b, w2.y, x2);
            ffma2(z[r].a, w3.x, x3); ffma2(z[r].b, w3.y, x3);
        }
    }
}

// z[r] += sum_{j<50} W[j][u][:] * h[r][j]
__device__ __forceinline__ void acc50(Z2 z[RPG], const float* __restrict__ Wb,
                                      const float* __restrict__ hb, int u)
{
#pragma unroll 2
    for (int jb = 0; jb < 48; jb += 4) {
        const ulonglong2 w0 = *(const ulonglong2*)(Wb + ((jb+0)*50 + u)*4);
        const ulonglong2 w1 = *(const ulonglong2*)(Wb + ((jb+1)*50 + u)*4);
        const ulonglong2 w2 = *(const ulonglong2*)(Wb + ((jb+2)*50 + u)*4);
        const ulonglong2 w3 = *(const ulonglong2*)(Wb + ((jb+3)*50 + u)*4);
#pragma unroll
        for (int r = 0; r < RPG; r++) {
            const float4 hv = *(const float4*)(hb + r*HPAD + jb);
            const u64 h0 = dup2(hv.x);
            const u64 h1 = dup2(hv.y);
            const u64 h2 = dup2(hv.z);
            const u64 h3 = dup2(hv.w);
            ffma2(z[r].a, w0.x, h0); ffma2(z[r].b, w0.y, h0);
            ffma2(z[r].a, w1.x, h1); ffma2(z[r].b, w1.y, h1);
            ffma2(z[r].a, w2.x, h2); ffma2(z[r].b, w2.y, h2);
            ffma2(z[r].a, w3.x, h3); ffma2(z[r].b, w3.y, h3);
        }
    }
    const ulonglong2 w48 = *(const ulonglong2*)(Wb + (48*50 + u)*4);
    const ulonglong2 w49 = *(const ulonglong2*)(Wb + (49*50 + u)*4);
#pragma unroll
    for (int r = 0; r < RPG; r++) {
        const u64 h48 = dup2(hb[r*HPAD + 48]);
        const u64 h49 = dup2(hb[r*HPAD + 49]);
        ffma2(z[r].a, w48.x, h48); ffma2(z[r].b, w48.y, h48);
        ffma2(z[r].a, w49.x, h49); ffma2(z[r].b, w49.y, h49);
    }
}

// merged double accumulation: z += Wa.h_a + Wb.h_b in one loop (2x ILP per iter)
__device__ __forceinline__ void acc50x2(Z2 z[RPG],
                                        const float* __restrict__ Wa,
                                        const float* __restrict__ ha,
                                        const float* __restrict__ Wb,
                                        const float* __restrict__ hb, int u)
{
#pragma unroll 2
    for (int jb = 0; jb < 48; jb += 4) {
        const ulonglong2 a0 = *(const ulonglong2*)(Wa + ((jb+0)*50 + u)*4);
        const ulonglong2 a1 = *(const ulonglong2*)(Wa + ((jb+1)*50 + u)*4);
        const ulonglong2 a2 = *(const ulonglong2*)(Wa + ((jb+2)*50 + u)*4);
        const ulonglong2 a3 = *(const ulonglong2*)(Wa + ((jb+3)*50 + u)*4);
        const ulonglong2 b0 = *(const ulonglong2*)(Wb + ((jb+0)*50 + u)*4);
        const ulonglong2 b1 = *(const ulonglong2*)(Wb + ((jb+1)*50 + u)*4);
        const ulonglong2 b2 = *(const ulonglong2*)(Wb + ((jb+2)*50 + u)*4);
        const ulonglong2 b3 = *(const ulonglong2*)(Wb + ((jb+3)*50 + u)*4);
#pragma unroll
        for (int r = 0; r < RPG; r++) {
            const float4 hva = *(const float4*)(ha + r*HPAD + jb);
            const float4 hvb = *(const float4*)(hb + r*HPAD + jb);
            const u64 ha0 = dup2(hva.x);
            const u64 ha1 = dup2(hva.y);
            const u64 ha2 = dup2(hva.z);
            const u64 ha3 = dup2(hva.w);
            ffma2(z[r].a, a0.x, ha0); ffma2(z[r].b, a0.y, ha0);
            ffma2(z[r].a, a1.x, ha1); ffma2(z[r].b, a1.y, ha1);
            ffma2(z[r].a, a2.x, ha2); ffma2(z[r].b, a2.y, ha2);
            ffma2(z[r].a, a3.x, ha3); ffma2(z[r].b, a3.y, ha3);
            const u64 hb0 = dup2(hvb.x);
            const u64 hb1 = dup2(hvb.y);
            const u64 hb2 = dup2(hvb.z);
            const u64 hb3 = dup2(hvb.w);
            ffma2(z[r].a, b0.x, hb0); ffma2(z[r].b, b0.y, hb0);
            ffma2(z[r].a, b1.x, hb1); ffma2(z[r].b, b1.y, hb1);
            ffma2(z[r].a, b2.x, hb2); ffma2(z[r].b, b2.y, hb2);
            ffma2(z[r].a, b3.x, hb3); ffma2(z[r].b, b3.y, hb3);
        }
    }
    const ulonglong2 a48 = *(const ulonglong2*)(Wa + (48*50 + u)*4);
    const ulonglong2 a49 = *(const ulonglong2*)(Wa + (49*50 + u)*4);
    const ulonglong2 b48 = *(const ulonglong2*)(Wb + (48*50 + u)*4);
    const ulonglong2 b49 = *(const ulonglong2*)(Wb + (49*50 + u)*4);
#pragma unroll
    for (int r = 0; r < RPG; r++) {
        const u64 ha48 = dup2(ha[r*HPAD + 48]);
        const u64 ha49 = dup2(ha[r*HPAD + 49]);
        const u64 hb48 = dup2(hb[r*HPAD + 48]);
        const u64 hb49 = dup2(hb[r*HPAD + 49]);
        ffma2(z[r].a, a48.x, ha48); ffma2(z[r].b, a48.y, ha48);
        ffma2(z[r].a, a49.x, ha49); ffma2(z[r].b, a49.y, ha49);
        ffma2(z[r].a, b48.x, hb48); ffma2(z[r].b, b48.y, hb48);
        ffma2(z[r].a, b49.x, hb49); ffma2(z[r].b, b49.y, hb49);
    }
}

__global__ void __launch_bounds__(NTHREADS, 1)
lstm_fused(const float* __restrict__ x,
           const float* __restrict__ Wih0, const float* __restrict__ Whh0,
           const float* __restrict__ bih0, const float* __restrict__ bhh0,
           const float* __restrict__ Wih1, const float* __restrict__ Whh1,
           const float* __restrict__ bih1, const float* __restrict__ bhh1,
           const float* __restrict__ Wih2, const float* __restrict__ Whh2,
           const float* __restrict__ bih2, const float* __restrict__ bhh2,
           const float* __restrict__ Wlin, const float* __restrict__ blin,
           float* __restrict__ out)
{
    extern __shared__ float sm[];
    float* W0 = sm + W0_OFF;
    float* W1 = sm + W1_OFF;
    float* W2 = sm + W2_OFF;
    float* HS = sm + HS_OFF;   // [3][BC][HPAD]
    float* XS = sm + XS_OFF;   // [BC][12]

    const int tid   = threadIdx.x;
    const int lane  = tid & 31;
    const int wid   = tid >> 5;
    const int grp   = wid >> 1;               // 0..7
    const int bid   = grp + 1;                // named barrier id
    const int r0    = grp * RPG;              // row base (4 rows)
    const int u     = (wid & 1) * 32 + lane;  // unit id
    const bool act  = (u < Hn);
    const int gtid  = tid & 63;               // thread id within group

    // ---- stage weights into shared with [k][u][gate] layout ----
    for (int idx = tid; idx < 12400; idx += NTHREADS) {
        const int g  = idx & 3;
        const int uu = (idx >> 2) % 50;
        const int k  = idx / 200;
        W0[idx] = (k < 12) ? Wih0[(g*50 + uu)*12 + k]
                           : Whh0[(g*50 + uu)*50 + (k - 12)];
    }
    for (int idx = tid; idx < 20000; idx += NTHREADS) {
        const int g  = idx & 3;
        const int uu = (idx >> 2) % 50;
        const int k  = idx / 200;
        W1[idx] = (k < 50) ? Wih1[(g*50 + uu)*50 + k]
                           : Whh1[(g*50 + uu)*50 + (k - 50)];
    }
    for (int idx = tid; idx < 20000; idx += NTHREADS) {
        const int g  = idx & 3;
        const int uu = (idx >> 2) % 50;
        const int k  = idx / 200;
        W2[idx] = (k < 50) ? Wih2[(g*50 + uu)*50 + k]
                           : Whh2[(g*50 + uu)*50 + (k - 50)];
    }
    for (int idx = tid; idx < 3*BC*HPAD; idx += NTHREADS) HS[idx] = 0.0f;

    u64 b0a = 0, b0b = 0, b1a = 0, b1b = 0, b2a = 0, b2b = 0;
    if (act) {
        b0a = pack2(bih0[u]       + bhh0[u],       bih0[50 + u]  + bhh0[50 + u]);
        b0b = pack2(bih0[100 + u] + bhh0[100 + u], bih0[150 + u] + bhh0[150 + u]);
        b1a = pack2(bih1[u]       + bhh1[u],       bih1[50 + u]  + bhh1[50 + u]);
        b1b = pack2(bih1[100 + u] + bhh1[100 + u], bih1[150 + u] + bhh1[150 + u]);
        b2a = pack2(bih2[u]       + bhh2[u],       bih2[50 + u]  + bhh2[50 + u]);
        b2b = pack2(bih2[100 + u] + bhh2[100 + u], bih2[150 + u] + bhh2[150 + u]);
    }

    float c0[RPG], c1[RPG], c2[RPG];
#pragma unroll
    for (int r = 0; r < RPG; r++) { c0[r] = 0.f; c1[r] = 0.f; c2[r] = 0.f; }

    const long long bbase = (long long)blockIdx.x * BC;
    const float* xb = x + bbase * (Tn * Fn);

    const int xrow = r0 + gtid / Fn;          // valid if gtid < 48
    const int xcol = gtid % Fn;

    float* HS0 = HS + 0*(BC*HPAD) + r0*HPAD;
    float* HS1 = HS + 1*(BC*HPAD) + r0*HPAD;
    float* HS2 = HS + 2*(BC*HPAD) + r0*HPAD;
    float* XSg = XS + r0*Fn;

    // prime x tile for phase 0 (covered by the __syncthreads below)
    if (gtid < RPG*Fn)
        XSg[gtid] = xb[xrow*(Tn*Fn) + 0*Fn + xcol];

    __syncthreads();

    // ===== skewed layer pipeline: phase p computes l0(p), l1(p-1), l2(p-2) =====
    // All reads are one phase-generation old; all writes in the write window.
    for (int p = 0; p < Tn + 2; p++) {
        const bool L0 = (p < Tn);
        const bool L1 = (p >= 1) && (p <= Tn);
        const bool L2 = (p >= 2);
        float hn0[RPG], hn1[RPG], hn2[RPG];
        Z2 z[RPG];

        if (act) {
            // ---- layer 0, time p ----
            if (L0) {
#pragma unroll
                for (int r = 0; r < RPG; r++) { z[r].a = b0a; z[r].b = b0b; }
                accX4(z, W0, XSg, u);
                acc50(z, W0 + 12*200, HS0, u);
#pragma unroll
                for (int r = 0; r < RPG; r++) {
                    float zi, zf, zg, zo;
                    unpack2(z[r].a, zi, zf);
                    unpack2(z[r].b, zg, zo);
                    const float ig = sigmoidf_(zi);
                    const float fg = sigmoidf_(zf);
                    const float gg = tanhf_(zg);
                    const float og = sigmoidf_(zo);
                    c0[r] = fg * c0[r] + ig * gg;
                    hn0[r] = og * tanhf_(c0[r]);
                }
            }
            // ---- layer 1, time p-1 ----
            if (L1) {
#pragma unroll
                for (int r = 0; r < RPG; r++) { z[r].a = b1a; z[r].b = b1b; }
                acc50x2(z, W1, HS0, W1 + 50*200, HS1, u);
#pragma unroll
                for (int r = 0; r < RPG; r++) {
                    float zi, zf, zg, zo;
                    unpack2(z[r].a, zi, zf);
                    unpack2(z[r].b, zg, zo);
                    const float ig = sigmoidf_(zi);
                    const float fg = sigmoidf_(zf);
                    const float gg = tanhf_(zg);
                    const float og = sigmoidf_(zo);
                    c1[r] = fg * c1[r] + ig * gg;
                    hn1[r] = og * tanhf_(c1[r]);
                }
            }
            // ---- layer 2, time p-2 ----
            if (L2) {
#pragma unroll
                for (int r = 0; r < RPG; r++) { z[r].a = b2a; z[r].b = b2b; }
                acc50x2(z, W2, HS1, W2 + 50*200, HS2, u);
#pragma unroll
                for (int r = 0; r < RPG; r++) {
                    float zi, zf, zg, zo;
                    unpack2(z[r].a, zi, zf);
                    unpack2(z[r].b, zg, zo);
                    const float ig = sigmoidf_(zi);
                    const float fg = sigmoidf_(zf);
                    const float gg = tanhf_(zg);
                    const float og = sigmoidf_(zo);
                    c2[r] = fg * c2[r] + ig * gg;
                    hn2[r] = og * tanhf_(c2[r]);
                }
            }
        }
        barg(bid);
        if (act) {
            if (L0) {
#pragma unroll
                for (int r = 0; r < RPG; r++) HS0[r*HPAD + u] = hn0[r];
            }
            if (L1) {
#pragma unroll
                for (int r = 0; r < RPG; r++) HS1[r*HPAD + u] = hn1[r];
            }
            if (L2) {
#pragma unroll
                for (int r = 0; r < RPG; r++) HS2[r*HPAD + u] = hn2[r];
            }
        }
        // x tile for phase p+1 (XS group-private; XS(p) last read this phase)
        if (p + 1 < Tn && gtid < RPG*Fn)
            XSg[gtid] = xb[xrow*(Tn*Fn) + (p+1)*Fn + xcol];
        barg(bid);
    }

    __syncthreads();

    // ---- final linear: out[b] = h2[b] . Wlin + blin ----
    if (tid < BC) {
        float s = blin[0];
#pragma unroll 10
        for (int uu = 0; uu < Hn; uu++)
            s += HS[2*(BC*HPAD) + tid*HPAD + uu] * Wlin[uu];
        out[bbase + tid] = s;
    }
}

extern "C" void kernel_launch(void* const* d_in, const int* in_sizes, int n_in,
                              void* d_out, int out_size)
{
    (void)in_sizes; (void)n_in; (void)out_size;
    const float* x    = (const float*)d_in[0];
    const float* Wih0 = (const float*)d_in[1];
    const float* Whh0 = (const float*)d_in[2];
    const float* bih0 = (const float*)d_in[3];
    const float* bhh0 = (const float*)d_in[4];
    const float* Wih1 = (const float*)d_in[5];
    const float* Whh1 = (const float*)d_in[6];
    const float* bih1 = (const float*)d_in[7];
    const float* bhh1 = (const float*)d_in[8];
    const float* Wih2 = (const float*)d_in[9];
    const float* Whh2 = (const float*)d_in[10];
    const float* bih2 = (const float*)d_in[11];
    const float* bhh2 = (const float*)d_in[12];
    const float* Wlin = (const float*)d_in[13];
    const float* blin = (const float*)d_in[14];
    float* out = (float*)d_out;

    cudaFuncSetAttribute(lstm_fused, cudaFuncAttributeMaxDynamicSharedMemorySize, SMEM_BYTES);
    lstm_fused<<<Bn / BC, NTHREADS, SMEM_BYTES>>>(
        x, Wih0, Whh0, bih0, bhh0,
        Wih1, Whh1, bih1, bhh1,
        Wih2, Whh2, bih2, bhh2,
        Wlin, blin, out);
}

// round 17
// speedup vs baseline: 1.3762x; 1.0143x over previous
#include <cuda_runtime.h>

// Problem constants
#define Tn 336
#define Fn 12
#define Hn 50
#define Bn 4096
#define BC 32          // batch rows per CTA
#define NTHREADS 512
#define HPAD 52        // h row stride (float4-aligned)
#define RPG 4          // rows per group (8 groups x 2 warps)

// shared memory float offsets
#define W0_OFF 0                 // layer0 combined [62][50][4]  = 12400 floats
#define W1_OFF 12400             // layer1 combined [100][50][4] = 20000
#define W2_OFF 32400             // layer2 combined [100][50][4] = 20000
#define HS_OFF 52400             // h state  3 * 32 * 52 = 4992
#define XS_OFF 57392             // x tile   32 * 12 = 384
#define SMEM_FLOATS 57776
#define SMEM_BYTES (SMEM_FLOATS * 4)

typedef unsigned long long u64;

// packed dual-fp32 FMA (sm_103a FFMA2): z += w * h (elementwise on 2 lanes)
__device__ __forceinline__ void ffma2(u64& z, const u64 w, const u64 h) {
    asm("fma.rn.f32x2 %0, %1, %2, %0;" : "+l"(z) : "l"(w), "l"(h));
}
// broadcast a scalar into both halves of a b64
__device__ __forceinline__ u64 dup2(const float s) {
    u64 r; asm("mov.b64 %0, {%1, %1};" : "=l"(r) : "f"(s)); return r;
}
__device__ __forceinline__ u64 pack2(const float lo, const float hi) {
    u64 r; asm("mov.b64 %0, {%1, %2};" : "=l"(r) : "f"(lo), "f"(hi)); return r;
}
__device__ __forceinline__ void unpack2(const u64 v, float& lo, float& hi) {
    asm("mov.b64 {%0, %1}, %2;" : "=f"(lo), "=f"(hi) : "l"(v));
}

__device__ __forceinline__ float sigmoidf_(float v) {
    return 1.0f / (1.0f + __expf(-v));
}
// precise-enough tanh: 1 - 2/(1+e^{2x}); ~1e-7 rel err
__device__ __forceinline__ float tanhf_(float v) {
    const float e = __expf(2.0f * v);
    return 1.0f - 2.0f / (e + 1.0f);
}

// named barrier for a 2-warp group (ids 1..8; 0 reserved for __syncthreads)
__device__ __forceinline__ void barg(int id) {
    asm volatile("bar.sync %0, 64;" :: "r"(id) : "memory");
}

struct Z2 { u64 a, b; };   // a = gates (i,f), b = gates (g,o)

// layer-0 x part: 12 k's over the 12-long x rows (stride Fn), float4 loads
__device__ __forceinline__ void accX4(Z2 z[RPG], const float* __restrict__ Wb,
                                      const float* __restrict__ xr, int u)
{
#pragma unroll
    for (int jb = 0; jb < 12; jb += 4) {
        const ulonglong2 w0 = *(const ulonglong2*)(Wb + ((jb+0)*50 + u)*4);
        const ulonglong2 w1 = *(const ulonglong2*)(Wb + ((jb+1)*50 + u)*4);
        const ulonglong2 w2 = *(const ulonglong2*)(Wb + ((jb+2)*50 + u)*4);
        const ulonglong2 w3 = *(const ulonglong2*)(Wb + ((jb+3)*50 + u)*4);
#pragma unroll
        for (int r = 0; r < RPG; r++) {
            const float4 xv = *(const float4*)(xr + r*Fn + jb);
            const u64 x0 = dup2(xv.x);
            const u64 x1 = dup2(xv.y);
            const u64 x2 = dup2(xv.z);
            const u64 x3 = dup2(xv.w);
            ffma2(z[r].a, w0.x, x0); ffma2(z[r].b, w0.y, x0);
            ffma2(z[r].a, w1.x, x1); ffma2(z[r].b, w1.y, x1);
            ffma2(z[r].a, w2.x, x2); ffma2(z[r].b, w2.y, x2);
            ffma2(z[r].a, w3.x, x3); ffma2(z[r].b, w3.y, x3);
        }
    }
}

// z[r] += sum_{j<50} W[j][u][:] * h[r][j]
__device__ __forceinline__ void acc50(Z2 z[RPG], const float* __restrict__ Wb,
                                      const float* __restrict__ hb, int u)
{
#pragma unroll 4
    for (int jb = 0; jb < 48; jb += 4) {
        const ulonglong2 w0 = *(const ulonglong2*)(Wb + ((jb+0)*50 + u)*4);
        const ulonglong2 w1 = *(const ulonglong2*)(Wb + ((jb+1)*50 + u)*4);
        const ulonglong2 w2 = *(const ulonglong2*)(Wb + ((jb+2)*50 + u)*4);
        const ulonglong2 w3 = *(const ulonglong2*)(Wb + ((jb+3)*50 + u)*4);
#pragma unroll
        for (int r = 0; r < RPG; r++) {
            const float4 hv = *(const float4*)(hb + r*HPAD + jb);
            const u64 h0 = dup2(hv.x);
            const u64 h1 = dup2(hv.y);
            const u64 h2 = dup2(hv.z);
            const u64 h3 = dup2(hv.w);
            ffma2(z[r].a, w0.x, h0); ffma2(z[r].b, w0.y, h0);
            ffma2(z[r].a, w1.x, h1); ffma2(z[r].b, w1.y, h1);
            ffma2(z[r].a, w2.x, h2); ffma2(z[r].b, w2.y, h2);
            ffma2(z[r].a, w3.x, h3); ffma2(z[r].b, w3.y, h3);
        }
    }
    const ulonglong2 w48 = *(const ulonglong2*)(Wb + (48*50 + u)*4);
    const ulonglong2 w49 = *(const ulonglong2*)(Wb + (49*50 + u)*4);
#pragma unroll
    for (int r = 0; r < RPG; r++) {
        const u64 h48 = dup2(hb[r*HPAD + 48]);
        const u64 h49 = dup2(hb[r*HPAD + 49]);
        ffma2(z[r].a, w48.x, h48); ffma2(z[r].b, w48.y, h48);
        ffma2(z[r].a, w49.x, h49); ffma2(z[r].b, w49.y, h49);
    }
}

// merged double accumulation: z += Wa.h_a + Wb.h_b in one loop (2x ILP per iter)
__device__ __forceinline__ void acc50x2(Z2 z[RPG],
                                        const float* __restrict__ Wa,
                                        const float* __restrict__ ha,
                                        const float* __restrict__ Wb,
                                        const float* __restrict__ hb, int u)
{
#pragma unroll 4
    for (int jb = 0; jb < 48; jb += 4) {
        const ulonglong2 a0 = *(const ulonglong2*)(Wa + ((jb+0)*50 + u)*4);
        const ulonglong2 a1 = *(const ulonglong2*)(Wa + ((jb+1)*50 + u)*4);
        const ulonglong2 a2 = *(const ulonglong2*)(Wa + ((jb+2)*50 + u)*4);
        const ulonglong2 a3 = *(const ulonglong2*)(Wa + ((jb+3)*50 + u)*4);
        const ulonglong2 b0 = *(const ulonglong2*)(Wb + ((jb+0)*50 + u)*4);
        const ulonglong2 b1 = *(const ulonglong2*)(Wb + ((jb+1)*50 + u)*4);
        const ulonglong2 b2 = *(const ulonglong2*)(Wb + ((jb+2)*50 + u)*4);
        const ulonglong2 b3 = *(const ulonglong2*)(Wb + ((jb+3)*50 + u)*4);
#pragma unroll
        for (int r = 0; r < RPG; r++) {
            const float4 hva = *(const float4*)(ha + r*HPAD + jb);
            const float4 hvb = *(const float4*)(hb + r*HPAD + jb);
            const u64 ha0 = dup2(hva.x);
            const u64 ha1 = dup2(hva.y);
            const u64 ha2 = dup2(hva.z);
            const u64 ha3 = dup2(hva.w);
            ffma2(z[r].a, a0.x, ha0); ffma2(z[r].b, a0.y, ha0);
            ffma2(z[r].a, a1.x, ha1); ffma2(z[r].b, a1.y, ha1);
            ffma2(z[r].a, a2.x, ha2); ffma2(z[r].b, a2.y, ha2);
            ffma2(z[r].a, a3.x, ha3); ffma2(z[r].b, a3.y, ha3);
            const u64 hb0 = dup2(hvb.x);
            const u64 hb1 = dup2(hvb.y);
            const u64 hb2 = dup2(hvb.z);
            const u64 hb3 = dup2(hvb.w);
            ffma2(z[r].a, b0.x, hb0); ffma2(z[r].b, b0.y, hb0);
            ffma2(z[r].a, b1.x, hb1); ffma2(z[r].b, b1.y, hb1);
            ffma2(z[r].a, b2.x, hb2); ffma2(z[r].b, b2.y, hb2);
            ffma2(z[r].a, b3.x, hb3); ffma2(z[r].b, b3.y, hb3);
        }
    }
    const ulonglong2 a48 = *(const ulonglong2*)(Wa + (48*50 + u)*4);
    const ulonglong2 a49 = *(const ulonglong2*)(Wa + (49*50 + u)*4);
    const ulonglong2 b48 = *(const ulonglong2*)(Wb + (48*50 + u)*4);
    const ulonglong2 b49 = *(const ulonglong2*)(Wb + (49*50 + u)*4);
#pragma unroll
    for (int r = 0; r < RPG; r++) {
        const u64 ha48 = dup2(ha[r*HPAD + 48]);
        const u64 ha49 = dup2(ha[r*HPAD + 49]);
        const u64 hb48 = dup2(hb[r*HPAD + 48]);
        const u64 hb49 = dup2(hb[r*HPAD + 49]);
        ffma2(z[r].a, a48.x, ha48); ffma2(z[r].b, a48.y, ha48);
        ffma2(z[r].a, a49.x, ha49); ffma2(z[r].b, a49.y, ha49);
        ffma2(z[r].a, b48.x, hb48); ffma2(z[r].b, b48.y, hb48);
        ffma2(z[r].a, b49.x, hb49); ffma2(z[r].b, b49.y, hb49);
    }
}

__global__ void __launch_bounds__(NTHREADS, 1)
lstm_fused(const float* __restrict__ x,
           const float* __restrict__ Wih0, const float* __restrict__ Whh0,
           const float* __restrict__ bih0, const float* __restrict__ bhh0,
           const float* __restrict__ Wih1, const float* __restrict__ Whh1,
           const float* __restrict__ bih1, const float* __restrict__ bhh1,
           const float* __restrict__ Wih2, const float* __restrict__ Whh2,
           const float* __restrict__ bih2, const float* __restrict__ bhh2,
           const float* __restrict__ Wlin, const float* __restrict__ blin,
           float* __restrict__ out)
{
    extern __shared__ float sm[];
    float* W0 = sm + W0_OFF;
    float* W1 = sm + W1_OFF;
    float* W2 = sm + W2_OFF;
    float* HS = sm + HS_OFF;   // [3][BC][HPAD]
    float* XS = sm + XS_OFF;   // [BC][12]

    const int tid   = threadIdx.x;
    const int lane  = tid & 31;
    const int wid   = tid >> 5;
    const int grp   = wid >> 1;               // 0..7
    const int bid   = grp + 1;                // named barrier id
    const int r0    = grp * RPG;              // row base (4 rows)
    const int u     = (wid & 1) * 32 + lane;  // unit id
    const bool act  = (u < Hn);
    const int gtid  = tid & 63;               // thread id within group

    // ---- stage weights into shared with [k][u][gate] layout ----
    for (int idx = tid; idx < 12400; idx += NTHREADS) {
        const int g  = idx & 3;
        const int uu = (idx >> 2) % 50;
        const int k  = idx / 200;
        W0[idx] = (k < 12) ? Wih0[(g*50 + uu)*12 + k]
                           : Whh0[(g*50 + uu)*50 + (k - 12)];
    }
    for (int idx = tid; idx < 20000; idx += NTHREADS) {
        const int g  = idx & 3;
        const int uu = (idx >> 2) % 50;
        const int k  = idx / 200;
        W1[idx] = (k < 50) ? Wih1[(g*50 + uu)*50 + k]
                           : Whh1[(g*50 + uu)*50 + (k - 50)];
    }
    for (int idx = tid; idx < 20000; idx += NTHREADS) {
        const int g  = idx & 3;
        const int uu = (idx >> 2) % 50;
        const int k  = idx / 200;
        W2[idx] = (k < 50) ? Wih2[(g*50 + uu)*50 + k]
                           : Whh2[(g*50 + uu)*50 + (k - 50)];
    }
    for (int idx = tid; idx < 3*BC*HPAD; idx += NTHREADS) HS[idx] = 0.0f;

    u64 b0a = 0, b0b = 0, b1a = 0, b1b = 0, b2a = 0, b2b = 0;
    if (act) {
        b0a = pack2(bih0[u]       + bhh0[u],       bih0[50 + u]  + bhh0[50 + u]);
        b0b = pack2(bih0[100 + u] + bhh0[100 + u], bih0[150 + u] + bhh0[150 + u]);
        b1a = pack2(bih1[u]       + bhh1[u],       bih1[50 + u]  + bhh1[50 + u]);
        b1b = pack2(bih1[100 + u] + bhh1[100 + u], bih1[150 + u] + bhh1[150 + u]);
        b2a = pack2(bih2[u]       + bhh2[u],       bih2[50 + u]  + bhh2[50 + u]);
        b2b = pack2(bih2[100 + u] + bhh2[100 + u], bih2[150 + u] + bhh2[150 + u]);
    }

    float c0[RPG], c1[RPG], c2[RPG];
#pragma unroll
    for (int r = 0; r < RPG; r++) { c0[r] = 0.f; c1[r] = 0.f; c2[r] = 0.f; }

    const long long bbase = (long long)blockIdx.x * BC;
    const float* xb = x + bbase * (Tn * Fn);

    const int xrow = r0 + gtid / Fn;          // valid if gtid < 48
    const int xcol = gtid % Fn;

    float* HS0 = HS + 0*(BC*HPAD) + r0*HPAD;
    float* HS1 = HS + 1*(BC*HPAD) + r0*HPAD;
    float* HS2 = HS + 2*(BC*HPAD) + r0*HPAD;
    float* XSg = XS + r0*Fn;

    // prime x tile for phase 0 (covered by the __syncthreads below)
    if (gtid < RPG*Fn)
        XSg[gtid] = xb[xrow*(Tn*Fn) + 0*Fn + xcol];

    __syncthreads();

    // ===== skewed layer pipeline: phase p computes l0(p), l1(p-1), l2(p-2) =====
    // All reads are one phase-generation old; all writes in the write window.
    for (int p = 0; p < Tn + 2; p++) {
        const bool L0 = (p < Tn);
        const bool L1 = (p >= 1) && (p <= Tn);
        const bool L2 = (p >= 2);
        float hn0[RPG], hn1[RPG], hn2[RPG];
        Z2 z[RPG];

        if (act) {
            // ---- layer 0, time p ----
            if (L0) {
#pragma unroll
                for (int r = 0; r < RPG; r++) { z[r].a = b0a; z[r].b = b0b; }
                accX4(z, W0, XSg, u);
                acc50(z, W0 + 12*200, HS0, u);
#pragma unroll
                for (int r = 0; r < RPG; r++) {
                    float zi, zf, zg, zo;
                    unpack2(z[r].a, zi, zf);
                    unpack2(z[r].b, zg, zo);
                    const float ig = sigmoidf_(zi);
                    const float fg = sigmoidf_(zf);
                    const float gg = tanhf_(zg);
                    const float og = sigmoidf_(zo);
                    c0[r] = fg * c0[r] + ig * gg;
                    hn0[r] = og * tanhf_(c0[r]);
                }
            }
            // ---- layer 1, time p-1 ----
            if (L1) {
#pragma unroll
                for (int r = 0; r < RPG; r++) { z[r].a = b1a; z[r].b = b1b; }
                acc50x2(z, W1, HS0, W1 + 50*200, HS1, u);
#pragma unroll
                for (int r = 0; r < RPG; r++) {
                    float zi, zf, zg, zo;
                    unpack2(z[r].a, zi, zf);
                    unpack2(z[r].b, zg, zo);
                    const float ig = sigmoidf_(zi);
                    const float fg = sigmoidf_(zf);
                    const float gg = tanhf_(zg);
                    const float og = sigmoidf_(zo);
                    c1[r] = fg * c1[r] + ig * gg;
                    hn1[r] = og * tanhf_(c1[r]);
                }
            }
            // ---- layer 2, time p-2 ----
            if (L2) {
#pragma unroll
                for (int r = 0; r < RPG; r++) { z[r].a = b2a; z[r].b = b2b; }
                acc50x2(z, W2, HS1, W2 + 50*200, HS2, u);
#pragma unroll
                for (int r = 0; r < RPG; r++) {
                    float zi, zf, zg, zo;
                    unpack2(z[r].a, zi, zf);
                    unpack2(z[r].b, zg, zo);
                    const float ig = sigmoidf_(zi);
                    const float fg = sigmoidf_(zf);
                    const float gg = tanhf_(zg);
                    const float og = sigmoidf_(zo);
                    c2[r] = fg * c2[r] + ig * gg;
                    hn2[r] = og * tanhf_(c2[r]);
                }
            }
        }
        barg(bid);
        if (act) {
            if (L0) {
#pragma unroll
                for (int r = 0; r < RPG; r++) HS0[r*HPAD + u] = hn0[r];
            }
            if (L1) {
#pragma unroll
                for (int r = 0; r < RPG; r++) HS1[r*HPAD + u] = hn1[r];
            }
            if (L2) {
#pragma unroll
                for (int r = 0; r < RPG; r++) HS2[r*HPAD + u] = hn2[r];
            }
        }
        // x tile for phase p+1 (XS group-private; XS(p) last read this phase)
        if (p + 1 < Tn && gtid < RPG*Fn)
            XSg[gtid] = xb[xrow*(Tn*Fn) + (p+1)*Fn + xcol];
        barg(bid);
    }

    __syncthreads();

    // ---- final linear: out[b] = h2[b] . Wlin + blin ----
    if (tid < BC) {
        float s = blin[0];
#pragma unroll 10
        for (int uu = 0; uu < Hn; uu++)
            s += HS[2*(BC*HPAD) + tid*HPAD + uu] * Wlin[uu];
        out[bbase + tid] = s;
    }
}

extern "C" void kernel_launch(void* const* d_in, const int* in_sizes, int n_in,
                              void* d_out, int out_size)
{
    (void)in_sizes; (void)n_in; (void)out_size;
    const float* x    = (const float*)d_in[0];
    const float* Wih0 = (const float*)d_in[1];
    const float* Whh0 = (const float*)d_in[2];
    const float* bih0 = (const float*)d_in[3];
    const float* bhh0 = (const float*)d_in[4];
    const float* Wih1 = (const float*)d_in[5];
    const float* Whh1 = (const float*)d_in[6];
    const float* bih1 = (const float*)d_in[7];
    const float* bhh1 = (const float*)d_in[8];
    const float* Wih2 = (const float*)d_in[9];
    const float* Whh2 = (const float*)d_in[10];
    const float* bih2 = (const float*)d_in[11];
    const float* bhh2 = (const float*)d_in[12];
    const float* Wlin = (const float*)d_in[13];
    const float* blin = (const float*)d_in[14];
    float* out = (float*)d_out;

    cudaFuncSetAttribute(lstm_fused, cudaFuncAttributeMaxDynamicSharedMemorySize, SMEM_BYTES);
    lstm_fused<<<Bn / BC, NTHREADS, SMEM_BYTES>>>(
        x, Wih0, Whh0, bih0, bhh0,
        Wih1, Whh1, bih1, bhh1,
        Wih2, Whh2, bih2, bhh2,
        Wlin, blin, out);
}